// round 7
// baseline (speedup 1.0000x reference)
#include <cuda_runtime.h>
#include <math.h>

#define L_SEQ 4096
#define D_MODEL 1536
#define N_HEADS 12
#define D_HEAD 128
#define C_HALF 64   // d/2
#define ROPE_C1 22
#define ROPE_C2 21

// ---------------- scratch (no allocations allowed) ----------------
__device__ float g_q[L_SEQ * D_MODEL];
__device__ float g_k[L_SEQ * D_MODEL];
__device__ float g_v[L_SEQ * D_MODEL];
__device__ float g_ao[L_SEQ * D_MODEL];

// ---------------- helpers ----------------
__device__ __forceinline__ unsigned f2tf(float f) {
  unsigned u;
  asm("cvt.rna.tf32.f32 %0, %1;" : "=r"(u) : "f"(f));
  return u;
}

__device__ __forceinline__ void mma8(float* c, const unsigned* a,
                                     const unsigned* b) {
  asm volatile(
      "mma.sync.aligned.m16n8k8.row.col.f32.tf32.tf32.f32 "
      "{%0,%1,%2,%3},{%4,%5,%6,%7},{%8,%9},{%0,%1,%2,%3};\n"
      : "+f"(c[0]), "+f"(c[1]), "+f"(c[2]), "+f"(c[3])
      : "r"(a[0]), "r"(a[1]), "r"(a[2]), "r"(a[3]), "r"(b[0]), "r"(b[1]));
}

// k-permuted smem layout: within each 8-wide k group, k lives at word
// position 2*(k&3) | (k>>2), so the MMA pair (k, k+4) is adjacent -> LDS.64.

// ---------------- TF32 GEMM: C[M,Nn] = A[M,K] * W[Nn,K]^T + bias -------------
// 128x128 tile, BK=32, 256 threads (8 warps, 2m x 4n), warp tile 64x32.
// gridDim.z selects (W,bias,C) triple -> merged QKV in one launch.
// Register-prefetch pipeline + k-permuted smem with LDS.64 fragment loads.
#define GS_STR 40  // 32 k-words + pad; 40 mod 32 = 8 -> conflict-free LDS.64
__global__ __launch_bounds__(256) void gemm_tf32(
    const float* __restrict__ Amat,
    const float* __restrict__ Wz0, const float* __restrict__ Wz1,
    const float* __restrict__ Wz2,
    const float* __restrict__ bz0, const float* __restrict__ bz1,
    const float* __restrict__ bz2,
    float* __restrict__ Cz0, float* __restrict__ Cz1, float* __restrict__ Cz2,
    int Mdim, int Ndim, int Kdim) {
  const int zi = blockIdx.z;
  const float* Wmat = (zi == 0) ? Wz0 : (zi == 1) ? Wz1 : Wz2;
  const float* bias = (zi == 0) ? bz0 : (zi == 1) ? bz1 : bz2;
  float* Cmat = (zi == 0) ? Cz0 : (zi == 1) ? Cz1 : Cz2;

  __shared__ unsigned As[128 * GS_STR];
  __shared__ unsigned Bs[128 * GS_STR];
  const int tid = threadIdx.x, lane = tid & 31, warp = tid >> 5;
  const int wm = warp >> 2, wn = warp & 3;
  const int m0 = blockIdx.y << 7, n0 = blockIdx.x << 7;
  const int K4 = Kdim >> 2;
  const float4* A4 = (const float4*)Amat;
  const float4* W4 = (const float4*)Wmat;
  const int lr = tid >> 3, lc = tid & 7;
  // permuted store base offset within row for this thread's 4 k-values
  const int stoff = ((lc >> 1) << 3) + (lc & 1);

  float acc[4][4][4];
#pragma unroll
  for (int mf = 0; mf < 4; mf++)
#pragma unroll
    for (int nf = 0; nf < 4; nf++)
#pragma unroll
      for (int u = 0; u < 4; u++) acc[mf][nf][u] = 0.f;

  float4 ar[4], wr[4];
#pragma unroll
  for (int i = 0; i < 4; i++) {
    ar[i] = A4[(size_t)(m0 + lr + 32 * i) * K4 + lc];
    wr[i] = W4[(size_t)(n0 + lr + 32 * i) * K4 + lc];
  }

  for (int k0 = 0; k0 < Kdim; k0 += 32) {
    __syncthreads();  // previous compute done; smem free
#pragma unroll
    for (int i = 0; i < 4; i++) {
      int base = (lr + 32 * i) * GS_STR + stoff;
      As[base + 0] = f2tf(ar[i].x);
      As[base + 2] = f2tf(ar[i].y);
      As[base + 4] = f2tf(ar[i].z);
      As[base + 6] = f2tf(ar[i].w);
      Bs[base + 0] = f2tf(wr[i].x);
      Bs[base + 2] = f2tf(wr[i].y);
      Bs[base + 4] = f2tf(wr[i].z);
      Bs[base + 6] = f2tf(wr[i].w);
    }
    __syncthreads();
    // prefetch next K-tile; latency hidden by the MMA section below
    const int kn = (k0 + 32 < Kdim) ? (k0 + 32) : k0;
#pragma unroll
    for (int i = 0; i < 4; i++) {
      ar[i] = A4[(size_t)(m0 + lr + 32 * i) * K4 + (kn >> 2) + lc];
      wr[i] = W4[(size_t)(n0 + lr + 32 * i) * K4 + (kn >> 2) + lc];
    }
#pragma unroll
    for (int s = 0; s < 4; s++) {
      const int koff = (s << 3) + ((lane & 3) << 1);
      uint2 a0[4], a1[4], bb[4];
#pragma unroll
      for (int mf = 0; mf < 4; mf++) {
        int r = (wm << 6) + (mf << 4) + (lane >> 2);
        a0[mf] = *(const uint2*)&As[r * GS_STR + koff];
        a1[mf] = *(const uint2*)&As[(r + 8) * GS_STR + koff];
      }
#pragma unroll
      for (int nf = 0; nf < 4; nf++) {
        int n = (wn << 5) + (nf << 3) + (lane >> 2);
        bb[nf] = *(const uint2*)&Bs[n * GS_STR + koff];
      }
#pragma unroll
      for (int mf = 0; mf < 4; mf++) {
        unsigned a[4] = {a0[mf].x, a1[mf].x, a0[mf].y, a1[mf].y};
#pragma unroll
        for (int nf = 0; nf < 4; nf++) {
          unsigned b[2] = {bb[nf].x, bb[nf].y};
          mma8(acc[mf][nf], a, b);
        }
      }
    }
  }
#pragma unroll
  for (int mf = 0; mf < 4; mf++) {
    int r = m0 + (wm << 6) + (mf << 4) + (lane >> 2);
#pragma unroll
    for (int nf = 0; nf < 4; nf++) {
      int c = n0 + (wn << 5) + (nf << 3) + ((lane & 3) << 1);
      float bb0 = bias[c], bb1 = bias[c + 1];
      float2 o0 = {acc[mf][nf][0] + bb0, acc[mf][nf][1] + bb1};
      *(float2*)&Cmat[(size_t)r * Ndim + c] = o0;
      float2 o1 = {acc[mf][nf][2] + bb0, acc[mf][nf][3] + bb1};
      *(float2*)&Cmat[(size_t)(r + 8) * Ndim + c] = o1;
    }
  }
}

// ---------------- fused RMSNorm (* g) + interleaved RoPE ----------------
// grid (L, 2): y=0 -> q buffer with gq, y=1 -> k buffer with gk
__global__ __launch_bounds__(256) void rmsnorm_rope(
    float* __restrict__ bufq, float* __restrict__ bufk,
    const float* __restrict__ gqp, const float* __restrict__ gkp,
    const int* __restrict__ grid_sizes,
    const float* __restrict__ fcos, const float* __restrict__ fsin) {
  const int t = blockIdx.x;
  const int tid = threadIdx.x;
  float* row = ((blockIdx.y == 0) ? bufq : bufk) + (size_t)t * D_MODEL;
  const float* g = (blockIdx.y == 0) ? gqp : gkp;

  float ss = 0.f;
  for (int i = tid; i < D_MODEL; i += 256) {
    float xv = row[i];
    ss += xv * xv;
  }
#pragma unroll
  for (int o = 16; o; o >>= 1) ss += __shfl_xor_sync(0xffffffffu, ss, o);
  __shared__ float red[8];
  if ((tid & 31) == 0) red[tid >> 5] = ss;

  const int f = grid_sizes[0], h = grid_sizes[1], w = grid_sizes[2];
  const int sl = f * h * w;

  __shared__ float cs[C_HALF], sn[C_HALF];
  if (t < sl && tid < C_HALF) {
    int fi = t / (h * w);
    int rem = t - fi * h * w;
    int hi = rem / w;
    int wi = rem - hi * w;
    int jj = tid;
    int rowp = (jj < ROPE_C1) ? fi : ((jj < ROPE_C1 + ROPE_C2) ? hi : wi);
    cs[jj] = fcos[rowp * C_HALF + jj];
    sn[jj] = fsin[rowp * C_HALF + jj];
  }
  __syncthreads();
  float tot = red[0] + red[1] + red[2] + red[3] + red[4] + red[5] + red[6] + red[7];
  float rinv = rsqrtf(tot * (1.0f / D_MODEL) + 1e-6f);

  if (t < sl) {
    for (int p = tid; p < N_HEADS * C_HALF; p += 256) {
      int head = p >> 6;
      int jj = p & 63;
      int i0 = head * D_HEAD + 2 * jj;
      float y0 = row[i0] * rinv * g[i0];
      float y1 = row[i0 + 1] * rinv * g[i0 + 1];
      float cv = cs[jj], sv = sn[jj];
      row[i0] = y0 * cv - y1 * sv;
      row[i0 + 1] = y0 * sv + y1 * cv;
    }
  } else {
    for (int i = tid; i < D_MODEL; i += 256) row[i] = row[i] * rinv * g[i];
  }
}

// ---------------- TF32 flash attention ----------------
// grid (L/128, N_HEADS), 256 threads (8 warps). Q tile 128, KV tile 64.
// Warp w owns S/O rows 16w..16w+15. Softmax fully in registers.
// K/V tiles register-prefetched; Qs/Ks/Ps k-permuted for LDS.64 fragments.
#define QS_STR 136  // 128 + pad; 136 mod 32 = 8
#define PS_STR 72   // 64 + pad
#define ATTN_SMEM (((128 + 64 + 64) * QS_STR + 128 * PS_STR) * 4)

__global__ __launch_bounds__(256) void attn_tf32(
    const float* __restrict__ q, const float* __restrict__ k,
    const float* __restrict__ v, const int* __restrict__ seq_lens,
    float* __restrict__ o) {
  extern __shared__ unsigned sm[];
  unsigned* Qs = sm;                  // [128][136] k-permuted
  unsigned* Ks = Qs + 128 * QS_STR;   // [64][136] k-permuted
  unsigned* Vs = Ks + 64 * QS_STR;    // [64][136] linear (k-major rows)
  unsigned* Ps = Vs + 64 * QS_STR;    // [128][72] k-permuted

  const int tid = threadIdx.x, lane = tid & 31, warp = tid >> 5;
  const int q0 = blockIdx.x << 7, head = blockIdx.y;
  const int seqlen = seq_lens[0];
  const float4* q4 = (const float4*)q;
  const float4* k4 = (const float4*)k;
  const float4* v4 = (const float4*)v;
  const int rs4 = D_MODEL / 4;        // 384
  const int h4 = head * (D_HEAD / 4); // head*32
  const float scq = 0.08838834764831845f;  // 1/sqrt(128)
  const int rq = (lane >> 2);
  const int r_own = (warp << 4) + rq;      // this thread's row (and +8)
  const int ldr = tid >> 5, ldc = tid & 31;  // loader row/col4
  const int stoff = ((ldc >> 1) << 3) + (ldc & 1);  // permuted store base
  // permuted store positions for P (k = 2t, 2t+1 with t = lane&3)
  const int tq = lane & 3;
  const int pp0 = (tq < 2) ? (tq << 2) : ((tq << 2) - 7);
  const int pp1 = pp0 + 2;

  // load + scale + cvt Q tile (permuted)
#pragma unroll
  for (int i = 0; i < 16; i++) {
    int r = ldr + (i << 3);
    float4 t = q4[(size_t)(q0 + r) * rs4 + h4 + ldc];
    int base = r * QS_STR + stoff;
    Qs[base + 0] = f2tf(t.x * scq);
    Qs[base + 2] = f2tf(t.y * scq);
    Qs[base + 4] = f2tf(t.z * scq);
    Qs[base + 6] = f2tf(t.w * scq);
  }

  // prefetch first KV tile into registers
  float4 kr[8], vr[8];
#pragma unroll
  for (int i = 0; i < 8; i++) {
    int r = ldr + (i << 3);
    kr[i] = k4[(size_t)r * rs4 + h4 + ldc];
    vr[i] = v4[(size_t)r * rs4 + h4 + ldc];
  }

  float m0r = -INFINITY, m1r = -INFINITY, l0 = 0.f, l1 = 0.f;
  float oac[16][4];
#pragma unroll
  for (int j = 0; j < 16; j++)
#pragma unroll
    for (int u = 0; u < 4; u++) oac[j][u] = 0.f;

  for (int kt = 0; kt < 64; kt++) {
    __syncthreads();  // prev PV done: Ks/Vs free (and Qs ready on iter 0)
#pragma unroll
    for (int i = 0; i < 8; i++) {
      int r = ldr + (i << 3);
      int base = r * QS_STR + stoff;
      Ks[base + 0] = f2tf(kr[i].x);
      Ks[base + 2] = f2tf(kr[i].y);
      Ks[base + 4] = f2tf(kr[i].z);
      Ks[base + 6] = f2tf(kr[i].w);
      uint4 uv = {f2tf(vr[i].x), f2tf(vr[i].y), f2tf(vr[i].z), f2tf(vr[i].w)};
      *(uint4*)&Vs[r * QS_STR + (ldc << 2)] = uv;
    }
    __syncthreads();

    // prefetch next KV tile (latency hidden behind QK+softmax+PV)
    {
      const int ktn = (kt < 63) ? (kt + 1) : kt;
#pragma unroll
      for (int i = 0; i < 8; i++) {
        int r = (ktn << 6) + ldr + (i << 3);
        kr[i] = k4[(size_t)r * rs4 + h4 + ldc];
        vr[i] = v4[(size_t)r * rs4 + h4 + ldc];
      }
    }

    // S = Q K^T : warp rows 16w..16w+15, all 64 cols, k=128
    float sacc[8][4];
#pragma unroll
    for (int j = 0; j < 8; j++)
#pragma unroll
      for (int u = 0; u < 4; u++) sacc[j][u] = 0.f;

#pragma unroll
    for (int s = 0; s < 16; s++) {
      int koff = (s << 3) + (tq << 1);
      uint2 qa0 = *(const uint2*)&Qs[r_own * QS_STR + koff];
      uint2 qa1 = *(const uint2*)&Qs[(r_own + 8) * QS_STR + koff];
      unsigned a[4] = {qa0.x, qa1.x, qa0.y, qa1.y};
#pragma unroll
      for (int j = 0; j < 8; j++) {
        int n = (j << 3) + rq;
        uint2 kb = *(const uint2*)&Ks[n * QS_STR + koff];
        unsigned b[2] = {kb.x, kb.y};
        mma8(sacc[j], a, b);
      }
    }

    // mask (only triggers on the ragged tail)
    if (((kt << 6) + 63) >= seqlen) {
#pragma unroll
      for (int j = 0; j < 8; j++) {
        int c = (kt << 6) + (j << 3) + (tq << 1);
        if (c >= seqlen) { sacc[j][0] = -1e30f; sacc[j][2] = -1e30f; }
        if (c + 1 >= seqlen) { sacc[j][1] = -1e30f; sacc[j][3] = -1e30f; }
      }
    }

    // register softmax: rows r_own (c0,c1) and r_own+8 (c2,c3)
    float mx0 = -INFINITY, mx1 = -INFINITY;
#pragma unroll
    for (int j = 0; j < 8; j++) {
      mx0 = fmaxf(mx0, fmaxf(sacc[j][0], sacc[j][1]));
      mx1 = fmaxf(mx1, fmaxf(sacc[j][2], sacc[j][3]));
    }
    mx0 = fmaxf(mx0, __shfl_xor_sync(0xffffffffu, mx0, 1));
    mx0 = fmaxf(mx0, __shfl_xor_sync(0xffffffffu, mx0, 2));
    mx1 = fmaxf(mx1, __shfl_xor_sync(0xffffffffu, mx1, 1));
    mx1 = fmaxf(mx1, __shfl_xor_sync(0xffffffffu, mx1, 2));
    float mn0 = fmaxf(m0r, mx0), mn1 = fmaxf(m1r, mx1);
    float co0 = __expf(m0r - mn0), co1 = __expf(m1r - mn1);
    float s0 = 0.f, s1 = 0.f;
#pragma unroll
    for (int j = 0; j < 8; j++) {
      float p0 = __expf(sacc[j][0] - mn0);
      float p1 = __expf(sacc[j][1] - mn0);
      float p2 = __expf(sacc[j][2] - mn1);
      float p3 = __expf(sacc[j][3] - mn1);
      s0 += p0 + p1;
      s1 += p2 + p3;
      int gb0 = r_own * PS_STR + (j << 3);
      int gb1 = (r_own + 8) * PS_STR + (j << 3);
      Ps[gb0 + pp0] = f2tf(p0);
      Ps[gb0 + pp1] = f2tf(p1);
      Ps[gb1 + pp0] = f2tf(p2);
      Ps[gb1 + pp1] = f2tf(p3);
    }
    s0 += __shfl_xor_sync(0xffffffffu, s0, 1);
    s0 += __shfl_xor_sync(0xffffffffu, s0, 2);
    s1 += __shfl_xor_sync(0xffffffffu, s1, 1);
    s1 += __shfl_xor_sync(0xffffffffu, s1, 2);
    l0 = l0 * co0 + s0;
    l1 = l1 * co1 + s1;
    m0r = mn0;
    m1r = mn1;
#pragma unroll
    for (int j = 0; j < 16; j++) {
      oac[j][0] *= co0;
      oac[j][1] *= co0;
      oac[j][2] *= co1;
      oac[j][3] *= co1;
    }
    __syncwarp();  // Ps rows are per-warp private; warp-level visibility only

    // O += P V : warp rows 16w.., n=128, k=64
#pragma unroll
    for (int s = 0; s < 8; s++) {
      int koff = (s << 3) + (tq << 1);
      uint2 pa0 = *(const uint2*)&Ps[r_own * PS_STR + koff];
      uint2 pa1 = *(const uint2*)&Ps[(r_own + 8) * PS_STR + koff];
      unsigned a[4] = {pa0.x, pa1.x, pa0.y, pa1.y};
      int kk = (s << 3) + tq;
#pragma unroll
      for (int j = 0; j < 16; j++) {
        int n = (j << 3) + rq;
        unsigned b[2] = {Vs[kk * QS_STR + n], Vs[(kk + 4) * QS_STR + n]};
        mma8(oac[j], a, b);
      }
    }
  }

  float i0 = 1.f / l0, i1 = 1.f / l1;
#pragma unroll
  for (int j = 0; j < 16; j++) {
    int c = (j << 3) + (tq << 1);
    float2 a = {oac[j][0] * i0, oac[j][1] * i0};
    *(float2*)&o[(size_t)(q0 + r_own) * D_MODEL + head * D_HEAD + c] = a;
    float2 b = {oac[j][2] * i1, oac[j][3] * i1};
    *(float2*)&o[(size_t)(q0 + r_own + 8) * D_MODEL + head * D_HEAD + c] = b;
  }
}

// ---------------- launch ----------------
extern "C" void kernel_launch(void* const* d_in, const int* in_sizes, int n_in,
                              void* d_out, int out_size) {
  const float* x = (const float*)d_in[0];
  const int* seq_lens = (const int*)d_in[1];
  const int* grid_sizes = (const int*)d_in[2];
  const float* fcos = (const float*)d_in[3];
  const float* fsin = (const float*)d_in[4];
  const float* Wq = (const float*)d_in[5];
  const float* bq = (const float*)d_in[6];
  const float* Wk = (const float*)d_in[7];
  const float* bk = (const float*)d_in[8];
  const float* Wv = (const float*)d_in[9];
  const float* bv = (const float*)d_in[10];
  const float* Wo = (const float*)d_in[11];
  const float* bo = (const float*)d_in[12];
  const float* gq = (const float*)d_in[13];
  const float* gk = (const float*)d_in[14];
  float* out = (float*)d_out;

  void *pq, *pk, *pv, *pao;
  cudaGetSymbolAddress(&pq, g_q);
  cudaGetSymbolAddress(&pk, g_k);
  cudaGetSymbolAddress(&pv, g_v);
  cudaGetSymbolAddress(&pao, g_ao);
  float* fq = (float*)pq;
  float* fk = (float*)pk;
  float* fv = (float*)pv;
  float* fao = (float*)pao;

  // fused QKV projection (z selects weights/output)
  dim3 gqkv(D_MODEL / 128, L_SEQ / 128, 3);
  gemm_tf32<<<gqkv, 256>>>(x, Wq, Wk, Wv, bq, bk, bv, fq, fk, fv,
                           L_SEQ, D_MODEL, D_MODEL);

  rmsnorm_rope<<<dim3(L_SEQ, 2), 256>>>(fq, fk, gq, gk, grid_sizes, fcos,
                                        fsin);

  cudaFuncSetAttribute(attn_tf32, cudaFuncAttributeMaxDynamicSharedMemorySize,
                       ATTN_SMEM);
  attn_tf32<<<dim3(L_SEQ / 128, N_HEADS), 256, ATTN_SMEM>>>(fq, fk, fv,
                                                            seq_lens, fao);

  dim3 go(D_MODEL / 128, L_SEQ / 128, 1);
  gemm_tf32<<<go, 256>>>(fao, Wo, Wo, Wo, bo, bo, bo, out, out, out,
                         L_SEQ, D_MODEL, D_MODEL);
}

// round 8
// speedup vs baseline: 1.2125x; 1.2125x over previous
#include <cuda_runtime.h>
#include <math.h>

#define L_SEQ 4096
#define D_MODEL 1536
#define N_HEADS 12
#define D_HEAD 128
#define C_HALF 64   // d/2
#define ROPE_C1 22
#define ROPE_C2 21
#define W_ELEMS (D_MODEL * D_MODEL)

// ---------------- scratch (no allocations allowed) ----------------
__device__ float g_q[L_SEQ * D_MODEL];
__device__ float g_k[L_SEQ * D_MODEL];
__device__ float g_v[L_SEQ * D_MODEL];
__device__ float g_ao[L_SEQ * D_MODEL];
__device__ float g_wr[4 * W_ELEMS];     // tf32-rounded Wq,Wk,Wv,Wo
__device__ float g_xr[L_SEQ * D_MODEL]; // tf32-rounded x

// ---------------- helpers ----------------
__device__ __forceinline__ unsigned f2tf(float f) {
  unsigned u;
  asm("cvt.rna.tf32.f32 %0, %1;" : "=r"(u) : "f"(f));
  return u;
}

__device__ __forceinline__ void mma8(float* c, const unsigned* a,
                                     const unsigned* b) {
  asm volatile(
      "mma.sync.aligned.m16n8k8.row.col.f32.tf32.tf32.f32 "
      "{%0,%1,%2,%3},{%4,%5,%6,%7},{%8,%9},{%0,%1,%2,%3};\n"
      : "+f"(c[0]), "+f"(c[1]), "+f"(c[2]), "+f"(c[3])
      : "r"(a[0]), "r"(a[1]), "r"(a[2]), "r"(a[3]), "r"(b[0]), "r"(b[1]));
}

// ---------------- tf32 pre-rounding of weights + x ----------------
__global__ __launch_bounds__(256) void round_tf32(
    const float* __restrict__ wq, const float* __restrict__ wk,
    const float* __restrict__ wv, const float* __restrict__ wo,
    const float* __restrict__ x) {
  const int zi = blockIdx.z;
  const float4* src;
  int n4;
  float4* dst;
  float4* wr4 = (float4*)g_wr;
  if (zi < 4) {
    src = (const float4*)((zi == 0) ? wq : (zi == 1) ? wk : (zi == 2) ? wv
                                                                      : wo);
    dst = wr4 + (size_t)zi * (W_ELEMS / 4);
    n4 = W_ELEMS / 4;
  } else {
    src = (const float4*)x;
    dst = (float4*)g_xr;
    n4 = (L_SEQ * D_MODEL) / 4;
  }
  int idx = blockIdx.x * 256 + threadIdx.x;
  if (idx < n4) {
    float4 t = src[idx];
    uint4 u = {f2tf(t.x), f2tf(t.y), f2tf(t.z), f2tf(t.w)};
    dst[idx] = *(float4*)&u;
  }
}

// ---------------- TF32 GEMM: C[M,Nn] = A[M,K] * W[Nn,K]^T + bias -------------
// 128x128 tile, BK=32, 256 threads (8 warps, 2m x 4n), warp tile 64x32.
// Inputs pre-rounded to tf32 values -> raw-bit STS.128, no cvt in loop.
// round_v: round C to tf32 values at epilogue (for the V output).
__global__ __launch_bounds__(256) void gemm_tf32(
    const float* __restrict__ Amat,
    const float* __restrict__ Wz0, const float* __restrict__ Wz1,
    const float* __restrict__ Wz2,
    const float* __restrict__ bz0, const float* __restrict__ bz1,
    const float* __restrict__ bz2,
    float* __restrict__ Cz0, float* __restrict__ Cz1, float* __restrict__ Cz2,
    int Mdim, int Ndim, int Kdim, int round_mask) {
  const int zi = blockIdx.z;
  const float* Wmat = (zi == 0) ? Wz0 : (zi == 1) ? Wz1 : Wz2;
  const float* bias = (zi == 0) ? bz0 : (zi == 1) ? bz1 : bz2;
  float* Cmat = (zi == 0) ? Cz0 : (zi == 1) ? Cz1 : Cz2;
  const bool do_round = ((round_mask >> zi) & 1) != 0;

  __shared__ unsigned As[128 * 36];
  __shared__ unsigned Bs[128 * 36];
  const int tid = threadIdx.x, lane = tid & 31, warp = tid >> 5;
  const int wm = warp >> 2, wn = warp & 3;
  const int m0 = blockIdx.y << 7, n0 = blockIdx.x << 7;
  const int K4 = Kdim >> 2;
  const float4* A4 = (const float4*)Amat;
  const float4* W4 = (const float4*)Wmat;
  const int lr = tid >> 3, lc = tid & 7;

  float acc[4][4][4];
#pragma unroll
  for (int mf = 0; mf < 4; mf++)
#pragma unroll
    for (int nf = 0; nf < 4; nf++)
#pragma unroll
      for (int u = 0; u < 4; u++) acc[mf][nf][u] = 0.f;

  float4 ar[4], wr[4];
#pragma unroll
  for (int i = 0; i < 4; i++) {
    ar[i] = A4[(size_t)(m0 + lr + 32 * i) * K4 + lc];
    wr[i] = W4[(size_t)(n0 + lr + 32 * i) * K4 + lc];
  }

  for (int k0 = 0; k0 < Kdim; k0 += 32) {
    __syncthreads();  // previous compute done; smem free
#pragma unroll
    for (int i = 0; i < 4; i++) {
      int base = (lr + 32 * i) * 36 + lc * 4;
      *(uint4*)&As[base] = *(uint4*)&ar[i];  // raw bits, already tf32-valued
      *(uint4*)&Bs[base] = *(uint4*)&wr[i];
    }
    __syncthreads();
    // prefetch next K-tile; latency hidden by the MMA section below
    const int kn = (k0 + 32 < Kdim) ? (k0 + 32) : k0;
#pragma unroll
    for (int i = 0; i < 4; i++) {
      ar[i] = A4[(size_t)(m0 + lr + 32 * i) * K4 + (kn >> 2) + lc];
      wr[i] = W4[(size_t)(n0 + lr + 32 * i) * K4 + (kn >> 2) + lc];
    }
#pragma unroll
    for (int s = 0; s < 4; s++) {
      const int kk = (s << 3) + (lane & 3);
      unsigned a[4][4], b[4][2];
#pragma unroll
      for (int mf = 0; mf < 4; mf++) {
        int r = (wm << 6) + (mf << 4) + (lane >> 2);
        a[mf][0] = As[r * 36 + kk];
        a[mf][1] = As[(r + 8) * 36 + kk];
        a[mf][2] = As[r * 36 + kk + 4];
        a[mf][3] = As[(r + 8) * 36 + kk + 4];
      }
#pragma unroll
      for (int nf = 0; nf < 4; nf++) {
        int n = (wn << 5) + (nf << 3) + (lane >> 2);
        b[nf][0] = Bs[n * 36 + kk];
        b[nf][1] = Bs[n * 36 + kk + 4];
      }
#pragma unroll
      for (int mf = 0; mf < 4; mf++)
#pragma unroll
        for (int nf = 0; nf < 4; nf++) mma8(acc[mf][nf], a[mf], b[nf]);
    }
  }
#pragma unroll
  for (int mf = 0; mf < 4; mf++) {
    int r = m0 + (wm << 6) + (mf << 4) + (lane >> 2);
#pragma unroll
    for (int nf = 0; nf < 4; nf++) {
      int c = n0 + (wn << 5) + (nf << 3) + ((lane & 3) << 1);
      float bb0 = bias[c], bb1 = bias[c + 1];
      float v00 = acc[mf][nf][0] + bb0, v01 = acc[mf][nf][1] + bb1;
      float v10 = acc[mf][nf][2] + bb0, v11 = acc[mf][nf][3] + bb1;
      if (do_round) {
        v00 = __uint_as_float(f2tf(v00));
        v01 = __uint_as_float(f2tf(v01));
        v10 = __uint_as_float(f2tf(v10));
        v11 = __uint_as_float(f2tf(v11));
      }
      float2 o0 = {v00, v01};
      *(float2*)&Cmat[(size_t)r * Ndim + c] = o0;
      float2 o1 = {v10, v11};
      *(float2*)&Cmat[(size_t)(r + 8) * Ndim + c] = o1;
    }
  }
}

// ---------------- fused RMSNorm (* g) + interleaved RoPE ----------------
// grid (L, 2): y=0 -> q buffer with gq (also *1/sqrt(d)), y=1 -> k with gk.
// Output is tf32-rounded so attention can skip cvt.
__global__ __launch_bounds__(256) void rmsnorm_rope(
    float* __restrict__ bufq, float* __restrict__ bufk,
    const float* __restrict__ gqp, const float* __restrict__ gkp,
    const int* __restrict__ grid_sizes,
    const float* __restrict__ fcos, const float* __restrict__ fsin) {
  const int t = blockIdx.x;
  const int tid = threadIdx.x;
  const int isq = (blockIdx.y == 0);
  float* row = (isq ? bufq : bufk) + (size_t)t * D_MODEL;
  const float* g = isq ? gqp : gkp;
  const float post = isq ? 0.08838834764831845f : 1.0f;  // 1/sqrt(128) for q

  float ss = 0.f;
  for (int i = tid; i < D_MODEL; i += 256) {
    float xv = row[i];
    ss += xv * xv;
  }
#pragma unroll
  for (int o = 16; o; o >>= 1) ss += __shfl_xor_sync(0xffffffffu, ss, o);
  __shared__ float red[8];
  if ((tid & 31) == 0) red[tid >> 5] = ss;

  const int f = grid_sizes[0], h = grid_sizes[1], w = grid_sizes[2];
  const int sl = f * h * w;

  __shared__ float cs[C_HALF], sn[C_HALF];
  if (t < sl && tid < C_HALF) {
    int fi = t / (h * w);
    int rem = t - fi * h * w;
    int hi = rem / w;
    int wi = rem - hi * w;
    int jj = tid;
    int rowp = (jj < ROPE_C1) ? fi : ((jj < ROPE_C1 + ROPE_C2) ? hi : wi);
    cs[jj] = fcos[rowp * C_HALF + jj];
    sn[jj] = fsin[rowp * C_HALF + jj];
  }
  __syncthreads();
  float tot = red[0] + red[1] + red[2] + red[3] + red[4] + red[5] + red[6] + red[7];
  float rinv = rsqrtf(tot * (1.0f / D_MODEL) + 1e-6f);

  if (t < sl) {
    for (int p = tid; p < N_HEADS * C_HALF; p += 256) {
      int head = p >> 6;
      int jj = p & 63;
      int i0 = head * D_HEAD + 2 * jj;
      float y0 = row[i0] * rinv * g[i0];
      float y1 = row[i0 + 1] * rinv * g[i0 + 1];
      float cv = cs[jj], sv = sn[jj];
      row[i0] = __uint_as_float(f2tf((y0 * cv - y1 * sv) * post));
      row[i0 + 1] = __uint_as_float(f2tf((y0 * sv + y1 * cv) * post));
    }
  } else {
    for (int i = tid; i < D_MODEL; i += 256)
      row[i] = __uint_as_float(f2tf(row[i] * rinv * g[i] * post));
  }
}

// ---------------- TF32 flash attention ----------------
// grid (L/128, N_HEADS), 256 threads (8 warps). Q tile 128, KV tile 64.
// Q pre-scaled+rounded, K/V pre-rounded -> raw-bit smem fills.
// Qs/Ks k-permuted (pair (k,k+4) adjacent) stored via shuffle-paired STS.128,
// loaded as LDS.64. Vs/Ps keep linear/uint2 layouts.
#define QS_STR 136  // 128 + pad; conflict-free for both STS.128 and LDS.64
#define PS_STR 68
#define ATTN_SMEM (((128 + 64 + 64) * QS_STR + 128 * PS_STR) * 4)

__global__ __launch_bounds__(256) void attn_tf32(
    const float* __restrict__ q, const float* __restrict__ k,
    const float* __restrict__ v, const int* __restrict__ seq_lens,
    float* __restrict__ o) {
  extern __shared__ unsigned sm[];
  unsigned* Qs = sm;                  // [128][136] k-permuted
  unsigned* Ks = Qs + 128 * QS_STR;   // [64][136] k-permuted
  unsigned* Vs = Ks + 64 * QS_STR;    // [64][136] linear
  unsigned* Ps = Vs + 64 * QS_STR;    // [128][68]

  const int tid = threadIdx.x, lane = tid & 31, warp = tid >> 5;
  const int q0 = blockIdx.x << 7, head = blockIdx.y;
  const int seqlen = seq_lens[0];
  const float4* q4 = (const float4*)q;
  const float4* k4 = (const float4*)k;
  const float4* v4 = (const float4*)v;
  const int rs4 = D_MODEL / 4;        // 384
  const int h4 = head * (D_HEAD / 4); // head*32
  const int rq = (lane >> 2);
  const int tq = lane & 3;
  const int r_own = (warp << 4) + rq;      // this thread's row (and +8)
  const int ldr = tid >> 5, ldc = tid & 31;  // loader row/col4
  const int odd = ldc & 1;
  // permuted-store word base: k-group (ldc>>1), halves split even/odd lane
  const int pbase = ((ldc >> 1) << 3) + (odd << 2);

  // load Q tile (already scaled+rounded): shuffle-pair into permuted layout
#pragma unroll
  for (int i = 0; i < 16; i++) {
    int r = ldr + (i << 3);
    float4 t = q4[(size_t)(q0 + r) * rs4 + h4 + ldc];
    float px = __shfl_xor_sync(0xffffffffu, t.x, 1);
    float py = __shfl_xor_sync(0xffffffffu, t.y, 1);
    float pz = __shfl_xor_sync(0xffffffffu, t.z, 1);
    float pw = __shfl_xor_sync(0xffffffffu, t.w, 1);
    uint4 u;
    if (!odd)
      u = make_uint4(__float_as_uint(t.x), __float_as_uint(px),
                     __float_as_uint(t.y), __float_as_uint(py));
    else
      u = make_uint4(__float_as_uint(pz), __float_as_uint(t.z),
                     __float_as_uint(pw), __float_as_uint(t.w));
    *(uint4*)&Qs[r * QS_STR + pbase] = u;
  }

  // prefetch first KV tile into registers
  float4 kr[8], vr[8];
#pragma unroll
  for (int i = 0; i < 8; i++) {
    int r = ldr + (i << 3);
    kr[i] = k4[(size_t)r * rs4 + h4 + ldc];
    vr[i] = v4[(size_t)r * rs4 + h4 + ldc];
  }

  float m0r = -INFINITY, m1r = -INFINITY, l0 = 0.f, l1 = 0.f;
  float oac[16][4];
#pragma unroll
  for (int j = 0; j < 16; j++)
#pragma unroll
    for (int u = 0; u < 4; u++) oac[j][u] = 0.f;

  for (int kt = 0; kt < 64; kt++) {
    __syncthreads();  // prev PV done: Ks/Vs free (and Qs ready on iter 0)
#pragma unroll
    for (int i = 0; i < 8; i++) {
      int r = ldr + (i << 3);
      // K: shuffle-pair permuted STS.128
      float px = __shfl_xor_sync(0xffffffffu, kr[i].x, 1);
      float py = __shfl_xor_sync(0xffffffffu, kr[i].y, 1);
      float pz = __shfl_xor_sync(0xffffffffu, kr[i].z, 1);
      float pw = __shfl_xor_sync(0xffffffffu, kr[i].w, 1);
      uint4 uk;
      if (!odd)
        uk = make_uint4(__float_as_uint(kr[i].x), __float_as_uint(px),
                        __float_as_uint(kr[i].y), __float_as_uint(py));
      else
        uk = make_uint4(__float_as_uint(pz), __float_as_uint(kr[i].z),
                        __float_as_uint(pw), __float_as_uint(kr[i].w));
      *(uint4*)&Ks[r * QS_STR + pbase] = uk;
      // V: linear raw copy
      *(uint4*)&Vs[r * QS_STR + (ldc << 2)] = *(uint4*)&vr[i];
    }
    __syncthreads();

    // prefetch next KV tile (latency hidden behind QK+softmax+PV)
    {
      const int ktn = (kt < 63) ? (kt + 1) : kt;
#pragma unroll
      for (int i = 0; i < 8; i++) {
        int r = (ktn << 6) + ldr + (i << 3);
        kr[i] = k4[(size_t)r * rs4 + h4 + ldc];
        vr[i] = v4[(size_t)r * rs4 + h4 + ldc];
      }
    }

    // S = Q K^T : warp rows 16w..16w+15, all 64 cols, k=128 (LDS.64 frags)
    float sacc[8][4];
#pragma unroll
    for (int j = 0; j < 8; j++)
#pragma unroll
      for (int u = 0; u < 4; u++) sacc[j][u] = 0.f;

#pragma unroll
    for (int s = 0; s < 16; s++) {
      int koff = (s << 3) + (tq << 1);
      uint2 qa0 = *(const uint2*)&Qs[r_own * QS_STR + koff];
      uint2 qa1 = *(const uint2*)&Qs[(r_own + 8) * QS_STR + koff];
      unsigned a[4] = {qa0.x, qa1.x, qa0.y, qa1.y};
#pragma unroll
      for (int j = 0; j < 8; j++) {
        int n = (j << 3) + rq;
        uint2 kb = *(const uint2*)&Ks[n * QS_STR + koff];
        unsigned b[2] = {kb.x, kb.y};
        mma8(sacc[j], a, b);
      }
    }

    // mask (only triggers on the ragged tail)
    if (((kt << 6) + 63) >= seqlen) {
#pragma unroll
      for (int j = 0; j < 8; j++) {
        int c = (kt << 6) + (j << 3) + (tq << 1);
        if (c >= seqlen) { sacc[j][0] = -1e30f; sacc[j][2] = -1e30f; }
        if (c + 1 >= seqlen) { sacc[j][1] = -1e30f; sacc[j][3] = -1e30f; }
      }
    }

    // register softmax: rows r_own (c0,c1) and r_own+8 (c2,c3)
    float mx0 = -INFINITY, mx1 = -INFINITY;
#pragma unroll
    for (int j = 0; j < 8; j++) {
      mx0 = fmaxf(mx0, fmaxf(sacc[j][0], sacc[j][1]));
      mx1 = fmaxf(mx1, fmaxf(sacc[j][2], sacc[j][3]));
    }
    mx0 = fmaxf(mx0, __shfl_xor_sync(0xffffffffu, mx0, 1));
    mx0 = fmaxf(mx0, __shfl_xor_sync(0xffffffffu, mx0, 2));
    mx1 = fmaxf(mx1, __shfl_xor_sync(0xffffffffu, mx1, 1));
    mx1 = fmaxf(mx1, __shfl_xor_sync(0xffffffffu, mx1, 2));
    float mn0 = fmaxf(m0r, mx0), mn1 = fmaxf(m1r, mx1);
    float co0 = __expf(m0r - mn0), co1 = __expf(m1r - mn1);
    float s0 = 0.f, s1 = 0.f;
#pragma unroll
    for (int j = 0; j < 8; j++) {
      float p0 = __expf(sacc[j][0] - mn0);
      float p1 = __expf(sacc[j][1] - mn0);
      float p2 = __expf(sacc[j][2] - mn1);
      float p3 = __expf(sacc[j][3] - mn1);
      s0 += p0 + p1;
      s1 += p2 + p3;
      int c = (j << 3) + (tq << 1);
      uint2 w0 = {f2tf(p0), f2tf(p1)};
      *(uint2*)&Ps[r_own * PS_STR + c] = w0;
      uint2 w1 = {f2tf(p2), f2tf(p3)};
      *(uint2*)&Ps[(r_own + 8) * PS_STR + c] = w1;
    }
    s0 += __shfl_xor_sync(0xffffffffu, s0, 1);
    s0 += __shfl_xor_sync(0xffffffffu, s0, 2);
    s1 += __shfl_xor_sync(0xffffffffu, s1, 1);
    s1 += __shfl_xor_sync(0xffffffffu, s1, 2);
    l0 = l0 * co0 + s0;
    l1 = l1 * co1 + s1;
    m0r = mn0;
    m1r = mn1;
#pragma unroll
    for (int j = 0; j < 16; j++) {
      oac[j][0] *= co0;
      oac[j][1] *= co0;
      oac[j][2] *= co1;
      oac[j][3] *= co1;
    }
    __syncwarp();  // Ps rows are per-warp private; warp-level visibility only

    // O += P V : warp rows 16w.., n=128, k=64
#pragma unroll
    for (int s = 0; s < 8; s++) {
      int kk = (s << 3) + tq;
      unsigned a[4];
      a[0] = Ps[r_own * PS_STR + kk];
      a[1] = Ps[(r_own + 8) * PS_STR + kk];
      a[2] = Ps[r_own * PS_STR + kk + 4];
      a[3] = Ps[(r_own + 8) * PS_STR + kk + 4];
#pragma unroll
      for (int j = 0; j < 16; j++) {
        int n = (j << 3) + rq;
        unsigned b[2] = {Vs[kk * QS_STR + n], Vs[(kk + 4) * QS_STR + n]};
        mma8(oac[j], a, b);
      }
    }
  }

  // epilogue: normalize + tf32-round (Wo gemm consumes raw bits)
  float i0 = 1.f / l0, i1 = 1.f / l1;
#pragma unroll
  for (int j = 0; j < 16; j++) {
    int c = (j << 3) + (tq << 1);
    float2 a = {__uint_as_float(f2tf(oac[j][0] * i0)),
                __uint_as_float(f2tf(oac[j][1] * i0))};
    *(float2*)&o[(size_t)(q0 + r_own) * D_MODEL + head * D_HEAD + c] = a;
    float2 b = {__uint_as_float(f2tf(oac[j][2] * i1)),
                __uint_as_float(f2tf(oac[j][3] * i1))};
    *(float2*)&o[(size_t)(q0 + r_own + 8) * D_MODEL + head * D_HEAD + c] = b;
  }
}

// ---------------- launch ----------------
extern "C" void kernel_launch(void* const* d_in, const int* in_sizes, int n_in,
                              void* d_out, int out_size) {
  const float* x = (const float*)d_in[0];
  const int* seq_lens = (const int*)d_in[1];
  const int* grid_sizes = (const int*)d_in[2];
  const float* fcos = (const float*)d_in[3];
  const float* fsin = (const float*)d_in[4];
  const float* Wq = (const float*)d_in[5];
  const float* bq = (const float*)d_in[6];
  const float* Wk = (const float*)d_in[7];
  const float* bk = (const float*)d_in[8];
  const float* Wv = (const float*)d_in[9];
  const float* bv = (const float*)d_in[10];
  const float* Wo = (const float*)d_in[11];
  const float* bo = (const float*)d_in[12];
  const float* gq = (const float*)d_in[13];
  const float* gk = (const float*)d_in[14];
  float* out = (float*)d_out;

  void *pq, *pk, *pv, *pao, *pwr, *pxr;
  cudaGetSymbolAddress(&pq, g_q);
  cudaGetSymbolAddress(&pk, g_k);
  cudaGetSymbolAddress(&pv, g_v);
  cudaGetSymbolAddress(&pao, g_ao);
  cudaGetSymbolAddress(&pwr, g_wr);
  cudaGetSymbolAddress(&pxr, g_xr);
  float* fq = (float*)pq;
  float* fk = (float*)pk;
  float* fv = (float*)pv;
  float* fao = (float*)pao;
  float* fwr = (float*)pwr;
  float* fxr = (float*)pxr;

  // pre-round weights + x to tf32 values
  {
    int n4max = (L_SEQ * D_MODEL) / 4;  // x is the largest
    dim3 gr((n4max + 255) / 256, 1, 5);
    round_tf32<<<gr, 256>>>(Wq, Wk, Wv, Wo, x);
  }

  // fused QKV projection (z selects weights/output); round only V (bit 2)
  dim3 gqkv(D_MODEL / 128, L_SEQ / 128, 3);
  gemm_tf32<<<gqkv, 256>>>(fxr, fwr, fwr + W_ELEMS, fwr + 2 * W_ELEMS,
                           bq, bk, bv, fq, fk, fv,
                           L_SEQ, D_MODEL, D_MODEL, /*round_mask=*/4);

  rmsnorm_rope<<<dim3(L_SEQ, 2), 256>>>(fq, fk, gq, gk, grid_sizes, fcos,
                                        fsin);

  cudaFuncSetAttribute(attn_tf32, cudaFuncAttributeMaxDynamicSharedMemorySize,
                       ATTN_SMEM);
  attn_tf32<<<dim3(L_SEQ / 128, N_HEADS), 256, ATTN_SMEM>>>(fq, fk, fv,
                                                            seq_lens, fao);

  dim3 go(D_MODEL / 128, L_SEQ / 128, 1);
  gemm_tf32<<<go, 256>>>(fao, fwr + 3 * W_ELEMS, fwr + 3 * W_ELEMS,
                         fwr + 3 * W_ELEMS, bo, bo, bo, out, out, out,
                         L_SEQ, D_MODEL, D_MODEL, /*round_mask=*/0);
}

// round 9
// speedup vs baseline: 2.0028x; 1.6518x over previous
#include <cuda_runtime.h>
#include <cuda_fp16.h>
#include <math.h>

#define L_SEQ 4096
#define D_MODEL 1536
#define N_HEADS 12
#define D_HEAD 128
#define C_HALF 64   // d/2
#define ROPE_C1 22
#define ROPE_C2 21
#define W_ELEMS (D_MODEL * D_MODEL)

// ---------------- scratch (no allocations allowed) ----------------
__device__ float g_q[L_SEQ * D_MODEL];   // f32 q from GEMM (pre-norm)
__device__ float g_k[L_SEQ * D_MODEL];   // f32 k from GEMM (pre-norm)
__device__ __half g_qh[L_SEQ * D_MODEL]; // fp16 q (normed+rope+scaled)
__device__ __half g_kh[L_SEQ * D_MODEL]; // fp16 k
__device__ __half g_vh[L_SEQ * D_MODEL]; // fp16 v
__device__ __half g_ao[L_SEQ * D_MODEL]; // fp16 attention output
__device__ __half g_xh[L_SEQ * D_MODEL]; // fp16 x
__device__ __half g_wh[4 * W_ELEMS];     // fp16 Wq,Wk,Wv,Wo

// ---------------- helpers ----------------
__device__ __forceinline__ void mma16(float* c, const unsigned* a,
                                      const unsigned* b) {
  asm volatile(
      "mma.sync.aligned.m16n8k16.row.col.f32.f16.f16.f32 "
      "{%0,%1,%2,%3},{%4,%5,%6,%7},{%8,%9},{%0,%1,%2,%3};\n"
      : "+f"(c[0]), "+f"(c[1]), "+f"(c[2]), "+f"(c[3])
      : "r"(a[0]), "r"(a[1]), "r"(a[2]), "r"(a[3]), "r"(b[0]), "r"(b[1]));
}

#define LDSM4(r0, r1, r2, r3, addr)                                      \
  asm volatile("ldmatrix.sync.aligned.m8n8.x4.shared.b16 {%0,%1,%2,%3},[%4];" \
               : "=r"(r0), "=r"(r1), "=r"(r2), "=r"(r3) : "r"(addr))
#define LDSM4T(r0, r1, r2, r3, addr)                                     \
  asm volatile(                                                          \
      "ldmatrix.sync.aligned.m8n8.x4.trans.shared.b16 {%0,%1,%2,%3},[%4];" \
      : "=r"(r0), "=r"(r1), "=r"(r2), "=r"(r3) : "r"(addr))

// ---------------- fp16 conversion of weights + x ----------------
__global__ __launch_bounds__(256) void to_half(
    const float* __restrict__ wq, const float* __restrict__ wk,
    const float* __restrict__ wv, const float* __restrict__ wo,
    const float* __restrict__ x) {
  const int zi = blockIdx.z;
  const float4* src;
  __half2* dst;
  int n4;
  if (zi < 4) {
    src = (const float4*)((zi == 0) ? wq : (zi == 1) ? wk : (zi == 2) ? wv
                                                                      : wo);
    dst = ((__half2*)g_wh) + (size_t)zi * (W_ELEMS / 2);
    n4 = W_ELEMS / 4;
  } else {
    src = (const float4*)x;
    dst = (__half2*)g_xh;
    n4 = (L_SEQ * D_MODEL) / 4;
  }
  int idx = blockIdx.x * 256 + threadIdx.x;
  if (idx < n4) {
    float4 t = src[idx];
    dst[2 * idx] = __floats2half2_rn(t.x, t.y);
    dst[2 * idx + 1] = __floats2half2_rn(t.z, t.w);
  }
}

// ---------------- fp16 GEMM: C[M,N] = A * W^T + bias ----------------
// 128x128 tile, BK=32, 256 threads (8 warps, 2m x 4n), warp 64x32.
// zi selects weights/bias/output; zi==2 writes fp16 (v), else fp32.
#define GSW 20  // row stride in words (32 halves + 8 pad)
__global__ __launch_bounds__(256) void gemm_f16(
    const __half* __restrict__ Ah,
    const __half* __restrict__ Wm0, const __half* __restrict__ Wm1,
    const __half* __restrict__ Wm2,
    const float* __restrict__ bz0, const float* __restrict__ bz1,
    const float* __restrict__ bz2,
    float* __restrict__ Cf0, float* __restrict__ Cf1,
    __half* __restrict__ Ch2) {
  const int zi = blockIdx.z;
  const __half* Wmat = (zi == 0) ? Wm0 : (zi == 1) ? Wm1 : Wm2;
  const float* bias = (zi == 0) ? bz0 : (zi == 1) ? bz1 : bz2;

  __shared__ unsigned As[128 * GSW];
  __shared__ unsigned Bs[128 * GSW];
  const unsigned as_b = (unsigned)__cvta_generic_to_shared(As);
  const unsigned bs_b = (unsigned)__cvta_generic_to_shared(Bs);
  const int tid = threadIdx.x, lane = tid & 31, warp = tid >> 5;
  const int wm = warp >> 2, wn = warp & 3;
  const int m0 = blockIdx.y << 7, n0 = blockIdx.x << 7;
  const int K8 = D_MODEL / 8;  // 192 uint4 per row
  const uint4* A4 = (const uint4*)Ah;
  const uint4* W4 = (const uint4*)Wmat;
  const int la = lane & 7, lb = (lane >> 3) & 1, lc2 = lane >> 4;
  const int rq = lane >> 2, tq = lane & 3;

  // ldmatrix base addresses (bytes)
  unsigned a_base[4], b_base[2];
#pragma unroll
  for (int mf = 0; mf < 4; mf++)
    a_base[mf] =
        as_b + ((wm * 64 + mf * 16 + la + 8 * lb) * GSW + 4 * lc2) * 4;
#pragma unroll
  for (int np = 0; np < 2; np++)
    b_base[np] = bs_b + ((wn * 32 + np * 16 + la + 8 * lc2) * GSW + 4 * lb) * 4;

  float acc[4][4][4];
#pragma unroll
  for (int mf = 0; mf < 4; mf++)
#pragma unroll
    for (int nf = 0; nf < 4; nf++)
#pragma unroll
      for (int u = 0; u < 4; u++) acc[mf][nf][u] = 0.f;

  const int ldrow0 = tid >> 2, ldc8 = tid & 3;
  uint4 ar2[2], wr2[2];
#pragma unroll
  for (int i = 0; i < 2; i++) {
    ar2[i] = A4[(size_t)(m0 + ldrow0 + 64 * i) * K8 + ldc8];
    wr2[i] = W4[(size_t)(n0 + ldrow0 + 64 * i) * K8 + ldc8];
  }

  for (int k0 = 0; k0 < D_MODEL; k0 += 32) {
    __syncthreads();
#pragma unroll
    for (int i = 0; i < 2; i++) {
      int base = (ldrow0 + 64 * i) * GSW + 4 * ldc8;
      *(uint4*)&As[base] = ar2[i];
      *(uint4*)&Bs[base] = wr2[i];
    }
    __syncthreads();
    const int kn = (k0 + 32 < D_MODEL) ? (k0 + 32) : k0;
#pragma unroll
    for (int i = 0; i < 2; i++) {
      ar2[i] = A4[(size_t)(m0 + ldrow0 + 64 * i) * K8 + (kn >> 3) + ldc8];
      wr2[i] = W4[(size_t)(n0 + ldrow0 + 64 * i) * K8 + (kn >> 3) + ldc8];
    }
#pragma unroll
    for (int s = 0; s < 2; s++) {
      unsigned a[4][4], bq[2][4];
#pragma unroll
      for (int mf = 0; mf < 4; mf++)
        LDSM4(a[mf][0], a[mf][1], a[mf][2], a[mf][3], a_base[mf] + 32 * s);
#pragma unroll
      for (int np = 0; np < 2; np++)
        LDSM4(bq[np][0], bq[np][1], bq[np][2], bq[np][3], b_base[np] + 32 * s);
#pragma unroll
      for (int mf = 0; mf < 4; mf++)
#pragma unroll
        for (int np = 0; np < 2; np++) {
          mma16(acc[mf][2 * np], a[mf], &bq[np][0]);
          mma16(acc[mf][2 * np + 1], a[mf], &bq[np][2]);
        }
    }
  }

#pragma unroll
  for (int mf = 0; mf < 4; mf++) {
    int r = m0 + wm * 64 + mf * 16 + rq;
#pragma unroll
    for (int nf = 0; nf < 4; nf++) {
      int c = n0 + wn * 32 + 8 * nf + 2 * tq;
      float bb0 = bias[c], bb1 = bias[c + 1];
      float v00 = acc[mf][nf][0] + bb0, v01 = acc[mf][nf][1] + bb1;
      float v10 = acc[mf][nf][2] + bb0, v11 = acc[mf][nf][3] + bb1;
      if (zi == 2) {
        *(__half2*)&Ch2[(size_t)r * D_MODEL + c] = __floats2half2_rn(v00, v01);
        *(__half2*)&Ch2[(size_t)(r + 8) * D_MODEL + c] =
            __floats2half2_rn(v10, v11);
      } else {
        float* Cf = (zi == 0) ? Cf0 : Cf1;
        float2 o0 = {v00, v01};
        *(float2*)&Cf[(size_t)r * D_MODEL + c] = o0;
        float2 o1 = {v10, v11};
        *(float2*)&Cf[(size_t)(r + 8) * D_MODEL + c] = o1;
      }
    }
  }
}

// ---------------- fused RMSNorm (* g) + RoPE -> fp16 ----------------
// grid (L, 2): y=0 -> q (with 1/sqrt(d) folded), y=1 -> k
__global__ __launch_bounds__(256) void rmsnorm_rope(
    const float* __restrict__ bufq, const float* __restrict__ bufk,
    __half* __restrict__ outq, __half* __restrict__ outk,
    const float* __restrict__ gqp, const float* __restrict__ gkp,
    const int* __restrict__ grid_sizes,
    const float* __restrict__ fcos, const float* __restrict__ fsin) {
  const int t = blockIdx.x;
  const int tid = threadIdx.x;
  const int isq = (blockIdx.y == 0);
  const float* row = (isq ? bufq : bufk) + (size_t)t * D_MODEL;
  __half2* orow = (__half2*)((isq ? outq : outk) + (size_t)t * D_MODEL);
  const float* g = isq ? gqp : gkp;
  const float post = isq ? 0.08838834764831845f : 1.0f;

  float ss = 0.f;
  for (int i = tid; i < D_MODEL; i += 256) {
    float xv = row[i];
    ss += xv * xv;
  }
#pragma unroll
  for (int o = 16; o; o >>= 1) ss += __shfl_xor_sync(0xffffffffu, ss, o);
  __shared__ float red[8];
  if ((tid & 31) == 0) red[tid >> 5] = ss;

  const int f = grid_sizes[0], h = grid_sizes[1], w = grid_sizes[2];
  const int sl = f * h * w;

  __shared__ float cs[C_HALF], sn[C_HALF];
  if (t < sl && tid < C_HALF) {
    int fi = t / (h * w);
    int rem = t - fi * h * w;
    int hi = rem / w;
    int wi = rem - hi * w;
    int jj = tid;
    int rowp = (jj < ROPE_C1) ? fi : ((jj < ROPE_C1 + ROPE_C2) ? hi : wi);
    cs[jj] = fcos[rowp * C_HALF + jj];
    sn[jj] = fsin[rowp * C_HALF + jj];
  }
  __syncthreads();
  float tot = red[0] + red[1] + red[2] + red[3] + red[4] + red[5] + red[6] + red[7];
  float rinv = rsqrtf(tot * (1.0f / D_MODEL) + 1e-6f);

  if (t < sl) {
    for (int p = tid; p < N_HEADS * C_HALF; p += 256) {
      int head = p >> 6;
      int jj = p & 63;
      int i0 = head * D_HEAD + 2 * jj;
      float y0 = row[i0] * rinv * g[i0];
      float y1 = row[i0 + 1] * rinv * g[i0 + 1];
      float cv = cs[jj], sv = sn[jj];
      orow[i0 >> 1] = __floats2half2_rn((y0 * cv - y1 * sv) * post,
                                        (y0 * sv + y1 * cv) * post);
    }
  } else {
    for (int p = tid; p < D_MODEL / 2; p += 256) {
      int i0 = 2 * p;
      orow[p] = __floats2half2_rn(row[i0] * rinv * g[i0] * post,
                                  row[i0 + 1] * rinv * g[i0 + 1] * post);
    }
  }
}

// ---------------- fp16 flash attention (ldmatrix + m16n8k16) -------------
// grid (L/128, N_HEADS), 256 threads (8 warps). Q tile 128, KV tile 64.
// smem (words): Qs [128][68], Ks [64][68], Vs [64][68], Ps [128][36]
#define QSW 68
#define PSW 36
#define ATTN_WORDS (128 * QSW + 64 * QSW + 64 * QSW + 128 * PSW)
#define ATTN_SMEM (ATTN_WORDS * 4)

__global__ __launch_bounds__(256) void attn_f16(
    const __half* __restrict__ qh, const __half* __restrict__ kh,
    const __half* __restrict__ vh, const int* __restrict__ seq_lens,
    __half* __restrict__ o) {
  extern __shared__ unsigned sm[];
  unsigned* Qs = sm;
  unsigned* Ks = Qs + 128 * QSW;
  unsigned* Vs = Ks + 64 * QSW;
  unsigned* Ps = Vs + 64 * QSW;
  const unsigned qs_b = (unsigned)__cvta_generic_to_shared(Qs);
  const unsigned ks_b = (unsigned)__cvta_generic_to_shared(Ks);
  const unsigned vs_b = (unsigned)__cvta_generic_to_shared(Vs);
  const unsigned ps_b = (unsigned)__cvta_generic_to_shared(Ps);

  const int tid = threadIdx.x, lane = tid & 31, warp = tid >> 5;
  const int q0 = blockIdx.x << 7, head = blockIdx.y;
  const int seqlen = seq_lens[0];
  const uint4* q4 = (const uint4*)qh;
  const uint4* k4 = (const uint4*)kh;
  const uint4* v4 = (const uint4*)vh;
  const int rs8 = D_MODEL / 8;   // 192 uint4 per row
  const int h8 = head * 16;      // head offset in uint4
  const int la = lane & 7, lb = (lane >> 3) & 1, lc2 = lane >> 4;
  const int rq = lane >> 2, tq = lane & 3;
  const int r_own = warp * 16 + rq;

  const unsigned a_off = qs_b + ((warp * 16 + la + 8 * lb) * QSW + 4 * lc2) * 4;
  const unsigned b_off = ks_b + ((la + 8 * lc2) * QSW + 4 * lb) * 4;
  const unsigned v_off = vs_b + ((la + 8 * lb) * QSW + 4 * lc2) * 4;
  const unsigned p_off = ps_b + ((warp * 16 + la + 8 * lb) * PSW + 4 * lc2) * 4;

  // load Q tile (pre-scaled fp16): 128 rows x 16 uint4
#pragma unroll
  for (int i = 0; i < 8; i++) {
    int idx = tid + (i << 8);
    int r = idx >> 4, c8 = idx & 15;
    *(uint4*)&Qs[r * QSW + 4 * c8] = q4[(size_t)(q0 + r) * rs8 + h8 + c8];
  }

  // prefetch first KV tile
  uint4 kr[4], vr[4];
#pragma unroll
  for (int i = 0; i < 4; i++) {
    int idx = tid + (i << 8);
    int r = idx >> 4, c8 = idx & 15;
    kr[i] = k4[(size_t)r * rs8 + h8 + c8];
    vr[i] = v4[(size_t)r * rs8 + h8 + c8];
  }

  float m0r = -INFINITY, m1r = -INFINITY, l0 = 0.f, l1 = 0.f;
  float oac[16][4];
#pragma unroll
  for (int j = 0; j < 16; j++)
#pragma unroll
    for (int u = 0; u < 4; u++) oac[j][u] = 0.f;

  for (int kt = 0; kt < 64; kt++) {
    __syncthreads();  // prev PV done (Ks/Vs free); Qs ready on iter 0
#pragma unroll
    for (int i = 0; i < 4; i++) {
      int idx = tid + (i << 8);
      int r = idx >> 4, c8 = idx & 15;
      *(uint4*)&Ks[r * QSW + 4 * c8] = kr[i];
      *(uint4*)&Vs[r * QSW + 4 * c8] = vr[i];
    }
    __syncthreads();

    {  // prefetch next KV tile
      const int ktn = (kt < 63) ? (kt + 1) : kt;
#pragma unroll
      for (int i = 0; i < 4; i++) {
        int idx = tid + (i << 8);
        int r = (ktn << 6) + (idx >> 4), c8 = idx & 15;
        kr[i] = k4[(size_t)r * rs8 + h8 + c8];
        vr[i] = v4[(size_t)r * rs8 + h8 + c8];
      }
    }

    // S = Q K^T : m16 (warp rows) x n64, k=128 in 8 k16-steps
    float sacc[8][4];
#pragma unroll
    for (int j = 0; j < 8; j++)
#pragma unroll
      for (int u = 0; u < 4; u++) sacc[j][u] = 0.f;

#pragma unroll
    for (int s = 0; s < 8; s++) {
      unsigned a[4];
      LDSM4(a[0], a[1], a[2], a[3], a_off + 32 * s);
#pragma unroll
      for (int jp = 0; jp < 4; jp++) {
        unsigned bb[4];
        LDSM4(bb[0], bb[1], bb[2], bb[3],
              b_off + jp * (16 * QSW * 4) + 32 * s);
        mma16(sacc[2 * jp], a, &bb[0]);
        mma16(sacc[2 * jp + 1], a, &bb[2]);
      }
    }

    // mask (ragged tail only)
    if (((kt << 6) + 63) >= seqlen) {
#pragma unroll
      for (int j = 0; j < 8; j++) {
        int c = (kt << 6) + (j << 3) + 2 * tq;
        if (c >= seqlen) { sacc[j][0] = -1e30f; sacc[j][2] = -1e30f; }
        if (c + 1 >= seqlen) { sacc[j][1] = -1e30f; sacc[j][3] = -1e30f; }
      }
    }

    // register softmax
    float mx0 = -INFINITY, mx1 = -INFINITY;
#pragma unroll
    for (int j = 0; j < 8; j++) {
      mx0 = fmaxf(mx0, fmaxf(sacc[j][0], sacc[j][1]));
      mx1 = fmaxf(mx1, fmaxf(sacc[j][2], sacc[j][3]));
    }
    mx0 = fmaxf(mx0, __shfl_xor_sync(0xffffffffu, mx0, 1));
    mx0 = fmaxf(mx0, __shfl_xor_sync(0xffffffffu, mx0, 2));
    mx1 = fmaxf(mx1, __shfl_xor_sync(0xffffffffu, mx1, 1));
    mx1 = fmaxf(mx1, __shfl_xor_sync(0xffffffffu, mx1, 2));
    float mn0 = fmaxf(m0r, mx0), mn1 = fmaxf(m1r, mx1);
    float co0 = __expf(m0r - mn0), co1 = __expf(m1r - mn1);
    float s0 = 0.f, s1 = 0.f;
#pragma unroll
    for (int j = 0; j < 8; j++) {
      float p0 = __expf(sacc[j][0] - mn0);
      float p1 = __expf(sacc[j][1] - mn0);
      float p2 = __expf(sacc[j][2] - mn1);
      float p3 = __expf(sacc[j][3] - mn1);
      s0 += p0 + p1;
      s1 += p2 + p3;
      __half2 hp0 = __floats2half2_rn(p0, p1);
      __half2 hp1 = __floats2half2_rn(p2, p3);
      Ps[r_own * PSW + 4 * j + tq] = *(unsigned*)&hp0;
      Ps[(r_own + 8) * PSW + 4 * j + tq] = *(unsigned*)&hp1;
    }
    s0 += __shfl_xor_sync(0xffffffffu, s0, 1);
    s0 += __shfl_xor_sync(0xffffffffu, s0, 2);
    s1 += __shfl_xor_sync(0xffffffffu, s1, 1);
    s1 += __shfl_xor_sync(0xffffffffu, s1, 2);
    l0 = l0 * co0 + s0;
    l1 = l1 * co1 + s1;
    m0r = mn0;
    m1r = mn1;
#pragma unroll
    for (int j = 0; j < 16; j++) {
      oac[j][0] *= co0;
      oac[j][1] *= co0;
      oac[j][2] *= co1;
      oac[j][3] *= co1;
    }
    __syncwarp();  // Ps rows are per-warp private

    // O += P V : m16 x n128, k=64 in 4 k16-steps; V via ldmatrix.trans
#pragma unroll
    for (int s = 0; s < 4; s++) {
      unsigned pa[4];
      LDSM4(pa[0], pa[1], pa[2], pa[3], p_off + 32 * s);
#pragma unroll
      for (int jp = 0; jp < 8; jp++) {
        unsigned vb[4];
        LDSM4T(vb[0], vb[1], vb[2], vb[3],
               v_off + s * (16 * QSW * 4) + 32 * jp);
        mma16(oac[2 * jp], pa, &vb[0]);
        mma16(oac[2 * jp + 1], pa, &vb[2]);
      }
    }
  }

  // epilogue: normalize, fp16-round, store
  float i0 = 1.f / l0, i1 = 1.f / l1;
  __half2* o2 = (__half2*)o;
#pragma unroll
  for (int j = 0; j < 16; j++) {
    int cw = head * 64 + 4 * j + tq;  // half2 index within row
    o2[(size_t)(q0 + r_own) * (D_MODEL / 2) + cw] =
        __floats2half2_rn(oac[j][0] * i0, oac[j][1] * i0);
    o2[(size_t)(q0 + r_own + 8) * (D_MODEL / 2) + cw] =
        __floats2half2_rn(oac[j][2] * i1, oac[j][3] * i1);
  }
}

// ---------------- launch ----------------
extern "C" void kernel_launch(void* const* d_in, const int* in_sizes, int n_in,
                              void* d_out, int out_size) {
  const float* x = (const float*)d_in[0];
  const int* seq_lens = (const int*)d_in[1];
  const int* grid_sizes = (const int*)d_in[2];
  const float* fcos = (const float*)d_in[3];
  const float* fsin = (const float*)d_in[4];
  const float* Wq = (const float*)d_in[5];
  const float* bq = (const float*)d_in[6];
  const float* Wk = (const float*)d_in[7];
  const float* bk = (const float*)d_in[8];
  const float* Wv = (const float*)d_in[9];
  const float* bv = (const float*)d_in[10];
  const float* Wo = (const float*)d_in[11];
  const float* bo = (const float*)d_in[12];
  const float* gq = (const float*)d_in[13];
  const float* gk = (const float*)d_in[14];
  float* out = (float*)d_out;

  void *pq, *pk, *pqh, *pkh, *pvh, *pao, *pxh, *pwh;
  cudaGetSymbolAddress(&pq, g_q);
  cudaGetSymbolAddress(&pk, g_k);
  cudaGetSymbolAddress(&pqh, g_qh);
  cudaGetSymbolAddress(&pkh, g_kh);
  cudaGetSymbolAddress(&pvh, g_vh);
  cudaGetSymbolAddress(&pao, g_ao);
  cudaGetSymbolAddress(&pxh, g_xh);
  cudaGetSymbolAddress(&pwh, g_wh);
  float* fq = (float*)pq;
  float* fk = (float*)pk;
  __half* fqh = (__half*)pqh;
  __half* fkh = (__half*)pkh;
  __half* fvh = (__half*)pvh;
  __half* fao = (__half*)pao;
  __half* fxh = (__half*)pxh;
  __half* fwh = (__half*)pwh;

  // convert weights + x to fp16
  {
    int n4max = (L_SEQ * D_MODEL) / 4;
    dim3 gr((n4max + 255) / 256, 1, 5);
    to_half<<<gr, 256>>>(Wq, Wk, Wv, Wo, x);
  }

  // fused QKV projection: z0->q f32, z1->k f32, z2->v fp16
  dim3 gqkv(D_MODEL / 128, L_SEQ / 128, 3);
  gemm_f16<<<gqkv, 256>>>(fxh, fwh, fwh + W_ELEMS, fwh + 2 * W_ELEMS,
                          bq, bk, bv, fq, fk, fvh);

  rmsnorm_rope<<<dim3(L_SEQ, 2), 256>>>(fq, fk, fqh, fkh, gq, gk, grid_sizes,
                                        fcos, fsin);

  cudaFuncSetAttribute(attn_f16, cudaFuncAttributeMaxDynamicSharedMemorySize,
                       ATTN_SMEM);
  attn_f16<<<dim3(L_SEQ / 128, N_HEADS), 256, ATTN_SMEM>>>(fqh, fkh, fvh,
                                                           seq_lens, fao);

  // output projection: A = fp16 attention out, Wo fp16, out f32
  dim3 go(D_MODEL / 128, L_SEQ / 128, 1);
  gemm_f16<<<go, 256>>>(fao, fwh + 3 * W_ELEMS, fwh + 3 * W_ELEMS,
                        fwh + 3 * W_ELEMS, bo, bo, bo, out, out, fvh);
}

// round 12
// speedup vs baseline: 2.2673x; 1.1321x over previous
#include <cuda_runtime.h>
#include <cuda_fp16.h>
#include <cstdint>
#include <stdint.h>
#include <math.h>

#define L_SEQ 4096
#define D_MODEL 1536
#define N_HEADS 12
#define D_HEAD 128
#define C_HALF 64   // d/2
#define ROPE_C1 22
#define ROPE_C2 21
#define W_ELEMS (D_MODEL * D_MODEL)

// ---------------- scratch (no allocations allowed) ----------------
__device__ float g_q[L_SEQ * D_MODEL];   // f32 q from GEMM (pre-norm)
__device__ float g_k[L_SEQ * D_MODEL];   // f32 k from GEMM (pre-norm)
__device__ __half g_qh[L_SEQ * D_MODEL]; // fp16 q (normed+rope+scaled)
__device__ __half g_kh[L_SEQ * D_MODEL]; // fp16 k
__device__ __half g_vh[L_SEQ * D_MODEL]; // fp16 v
__device__ __half g_ao[L_SEQ * D_MODEL]; // fp16 attention output
__device__ __half g_xh[L_SEQ * D_MODEL]; // fp16 x
__device__ __half g_wh[4 * W_ELEMS];     // fp16 Wq,Wk,Wv,Wo

// ---------------- mma helpers ----------------
__device__ __forceinline__ void mma16(float* c, const unsigned* a,
                                      const unsigned* b) {
  asm volatile(
      "mma.sync.aligned.m16n8k16.row.col.f32.f16.f16.f32 "
      "{%0,%1,%2,%3},{%4,%5,%6,%7},{%8,%9},{%0,%1,%2,%3};\n"
      : "+f"(c[0]), "+f"(c[1]), "+f"(c[2]), "+f"(c[3])
      : "r"(a[0]), "r"(a[1]), "r"(a[2]), "r"(a[3]), "r"(b[0]), "r"(b[1]));
}

#define LDSM4(r0, r1, r2, r3, addr)                                      \
  asm volatile("ldmatrix.sync.aligned.m8n8.x4.shared.b16 {%0,%1,%2,%3},[%4];" \
               : "=r"(r0), "=r"(r1), "=r"(r2), "=r"(r3) : "r"(addr))
#define LDSM4T(r0, r1, r2, r3, addr)                                     \
  asm volatile(                                                          \
      "ldmatrix.sync.aligned.m8n8.x4.trans.shared.b16 {%0,%1,%2,%3},[%4];" \
      : "=r"(r0), "=r"(r1), "=r"(r2), "=r"(r3) : "r"(addr))

// cp.async helpers (16B, cache-global)
#define CP_ASYNC16(dst, src)                                        \
  asm volatile("cp.async.cg.shared.global [%0], [%1], 16;" ::       \
                   "r"(dst), "l"(src))
#define CP_COMMIT() asm volatile("cp.async.commit_group;" ::: "memory")
#define CP_WAIT0() asm volatile("cp.async.wait_group 0;" ::: "memory")

// ---------------- fp16 conversion of weights + x ----------------
__global__ __launch_bounds__(256) void to_half(
    const float* __restrict__ wq, const float* __restrict__ wk,
    const float* __restrict__ wv, const float* __restrict__ wo,
    const float* __restrict__ x) {
  const int zi = blockIdx.z;
  const float4* src;
  __half2* dst;
  int n4;
  if (zi < 4) {
    src = (const float4*)((zi == 0) ? wq : (zi == 1) ? wk : (zi == 2) ? wv
                                                                      : wo);
    dst = ((__half2*)g_wh) + (size_t)zi * (W_ELEMS / 2);
    n4 = W_ELEMS / 4;
  } else {
    src = (const float4*)x;
    dst = (__half2*)g_xh;
    n4 = (L_SEQ * D_MODEL) / 4;
  }
  int idx = blockIdx.x * 256 + threadIdx.x;
  if (idx < n4) {
    float4 t = src[idx];
    dst[2 * idx] = __floats2half2_rn(t.x, t.y);
    dst[2 * idx + 1] = __floats2half2_rn(t.z, t.w);
  }
}

// ---------------- fp16 GEMM: C[M,N] = A * W^T + bias ----------------
// 128x128 tile, BK=64, 256 threads (8 warps, 2m x 4n), warp 64x32.
// zi selects weights/bias/output; zi==2 writes fp16 (v), else fp32.
#define GSW 36  // row stride in words (64 halves + 8 pad = 144B)
__global__ __launch_bounds__(256, 2) void gemm_f16(
    const __half* __restrict__ Ah,
    const __half* __restrict__ Wm0, const __half* __restrict__ Wm1,
    const __half* __restrict__ Wm2,
    const float* __restrict__ bz0, const float* __restrict__ bz1,
    const float* __restrict__ bz2,
    float* __restrict__ Cf0, float* __restrict__ Cf1,
    __half* __restrict__ Ch2) {
  const int zi = blockIdx.z;
  const __half* Wmat = (zi == 0) ? Wm0 : (zi == 1) ? Wm1 : Wm2;
  const float* bias = (zi == 0) ? bz0 : (zi == 1) ? bz1 : bz2;

  __shared__ unsigned As[128 * GSW];
  __shared__ unsigned Bs[128 * GSW];
  const unsigned as_b = (unsigned)__cvta_generic_to_shared(As);
  const unsigned bs_b = (unsigned)__cvta_generic_to_shared(Bs);
  const int tid = threadIdx.x, lane = tid & 31, warp = tid >> 5;
  const int wm = warp >> 2, wn = warp & 3;
  const int m0 = blockIdx.y << 7, n0 = blockIdx.x << 7;
  const int K8 = D_MODEL / 8;  // 192 uint4 per row
  const uint4* A4 = (const uint4*)Ah;
  const uint4* W4 = (const uint4*)Wmat;
  const int la = lane & 7, lb = (lane >> 3) & 1, lc2 = lane >> 4;
  const int rq = lane >> 2, tq = lane & 3;

  // ldmatrix base addresses (bytes); per k16-step add 32*s
  unsigned a_base[4], b_base[2];
#pragma unroll
  for (int mf = 0; mf < 4; mf++)
    a_base[mf] =
        as_b + ((wm * 64 + mf * 16 + la + 8 * lb) * GSW + 4 * lc2) * 4;
#pragma unroll
  for (int np = 0; np < 2; np++)
    b_base[np] = bs_b + ((wn * 32 + np * 16 + la + 8 * lc2) * GSW + 4 * lb) * 4;

  float acc[4][4][4];
#pragma unroll
  for (int mf = 0; mf < 4; mf++)
#pragma unroll
    for (int nf = 0; nf < 4; nf++)
#pragma unroll
      for (int u = 0; u < 4; u++) acc[mf][nf][u] = 0.f;

  // loader mapping: idx = tid + 256*i -> row = idx>>3 (0..127), c8 = idx&7
  const int ldrow = tid >> 3, ldc8 = tid & 7;
  uint4 ar[4], wr[4];
#pragma unroll
  for (int i = 0; i < 4; i++) {
    int r = ldrow + 32 * i;
    ar[i] = A4[(size_t)(m0 + r) * K8 + ldc8];
    wr[i] = W4[(size_t)(n0 + r) * K8 + ldc8];
  }

  for (int k0 = 0; k0 < D_MODEL; k0 += 64) {
    __syncthreads();
#pragma unroll
    for (int i = 0; i < 4; i++) {
      int r = ldrow + 32 * i;
      int base = r * GSW + 4 * ldc8;
      *(uint4*)&As[base] = ar[i];
      *(uint4*)&Bs[base] = wr[i];
    }
    __syncthreads();
    const int kn = (k0 + 64 < D_MODEL) ? (k0 + 64) : k0;
#pragma unroll
    for (int i = 0; i < 4; i++) {
      int r = ldrow + 32 * i;
      ar[i] = A4[(size_t)(m0 + r) * K8 + (kn >> 3) + ldc8];
      wr[i] = W4[(size_t)(n0 + r) * K8 + (kn >> 3) + ldc8];
    }
#pragma unroll
    for (int s = 0; s < 4; s++) {
      unsigned a[4][4], bq[2][4];
#pragma unroll
      for (int mf = 0; mf < 4; mf++)
        LDSM4(a[mf][0], a[mf][1], a[mf][2], a[mf][3], a_base[mf] + 32 * s);
#pragma unroll
      for (int np = 0; np < 2; np++)
        LDSM4(bq[np][0], bq[np][1], bq[np][2], bq[np][3], b_base[np] + 32 * s);
#pragma unroll
      for (int mf = 0; mf < 4; mf++)
#pragma unroll
        for (int np = 0; np < 2; np++) {
          mma16(acc[mf][2 * np], a[mf], &bq[np][0]);
          mma16(acc[mf][2 * np + 1], a[mf], &bq[np][2]);
        }
    }
  }

#pragma unroll
  for (int mf = 0; mf < 4; mf++) {
    int r = m0 + wm * 64 + mf * 16 + rq;
#pragma unroll
    for (int nf = 0; nf < 4; nf++) {
      int c = n0 + wn * 32 + 8 * nf + 2 * tq;
      float bb0 = bias[c], bb1 = bias[c + 1];
      float v00 = acc[mf][nf][0] + bb0, v01 = acc[mf][nf][1] + bb1;
      float v10 = acc[mf][nf][2] + bb0, v11 = acc[mf][nf][3] + bb1;
      if (zi == 2) {
        *(__half2*)&Ch2[(size_t)r * D_MODEL + c] = __floats2half2_rn(v00, v01);
        *(__half2*)&Ch2[(size_t)(r + 8) * D_MODEL + c] =
            __floats2half2_rn(v10, v11);
      } else {
        float* Cf = (zi == 0) ? Cf0 : Cf1;
        float2 o0 = {v00, v01};
        *(float2*)&Cf[(size_t)r * D_MODEL + c] = o0;
        float2 o1 = {v10, v11};
        *(float2*)&Cf[(size_t)(r + 8) * D_MODEL + c] = o1;
      }
    }
  }
}

// ---------------- fused RMSNorm (* g) + RoPE -> fp16 ----------------
// grid (L, 2): y=0 -> q (with 1/sqrt(d) folded), y=1 -> k
__global__ __launch_bounds__(256) void rmsnorm_rope(
    const float* __restrict__ bufq, const float* __restrict__ bufk,
    __half* __restrict__ outq, __half* __restrict__ outk,
    const float* __restrict__ gqp, const float* __restrict__ gkp,
    const int* __restrict__ grid_sizes,
    const float* __restrict__ fcos, const float* __restrict__ fsin) {
  const int t = blockIdx.x;
  const int tid = threadIdx.x;
  const int isq = (blockIdx.y == 0);
  const float* row = (isq ? bufq : bufk) + (size_t)t * D_MODEL;
  __half2* orow = (__half2*)((isq ? outq : outk) + (size_t)t * D_MODEL);
  const float* g = isq ? gqp : gkp;
  const float post = isq ? 0.08838834764831845f : 1.0f;

  float ss = 0.f;
  for (int i = tid; i < D_MODEL; i += 256) {
    float xv = row[i];
    ss += xv * xv;
  }
#pragma unroll
  for (int o = 16; o; o >>= 1) ss += __shfl_xor_sync(0xffffffffu, ss, o);
  __shared__ float red[8];
  if ((tid & 31) == 0) red[tid >> 5] = ss;

  const int f = grid_sizes[0], h = grid_sizes[1], w = grid_sizes[2];
  const int sl = f * h * w;

  __shared__ float cs[C_HALF], sn[C_HALF];
  if (t < sl && tid < C_HALF) {
    int fi = t / (h * w);
    int rem = t - fi * h * w;
    int hi = rem / w;
    int wi = rem - hi * w;
    int jj = tid;
    int rowp = (jj < ROPE_C1) ? fi : ((jj < ROPE_C1 + ROPE_C2) ? hi : wi);
    cs[jj] = fcos[rowp * C_HALF + jj];
    sn[jj] = fsin[rowp * C_HALF + jj];
  }
  __syncthreads();
  float tot = red[0] + red[1] + red[2] + red[3] + red[4] + red[5] + red[6] + red[7];
  float rinv = rsqrtf(tot * (1.0f / D_MODEL) + 1e-6f);

  if (t < sl) {
    for (int p = tid; p < N_HEADS * C_HALF; p += 256) {
      int head = p >> 6;
      int jj = p & 63;
      int i0 = head * D_HEAD + 2 * jj;
      float y0 = row[i0] * rinv * g[i0];
      float y1 = row[i0 + 1] * rinv * g[i0 + 1];
      float cv = cs[jj], sv = sn[jj];
      orow[i0 >> 1] = __floats2half2_rn((y0 * cv - y1 * sv) * post,
                                        (y0 * sv + y1 * cv) * post);
    }
  } else {
    for (int p = tid; p < D_MODEL / 2; p += 256) {
      int i0 = 2 * p;
      orow[p] = __floats2half2_rn(row[i0] * rinv * g[i0] * post,
                                  row[i0 + 1] * rinv * g[i0 + 1] * post);
    }
  }
}

// ---------------- fp16 flash attention (ldmatrix + m16n8k16) -------------
// grid (L/128, N_HEADS), 256 threads (8 warps). Q tile 128, KV tile 64.
// K/V filled via cp.async (no prefetch registers) -> regs <=128 -> 2 CTAs/SM;
// cross-CTA overlap hides the exposed load latency.
#define QSW 68
#define PSW 36
#define ATTN_WORDS (128 * QSW + 64 * QSW + 64 * QSW + 128 * PSW)
#define ATTN_SMEM (ATTN_WORDS * 4)

__global__ __launch_bounds__(256, 2) void attn_f16(
    const __half* __restrict__ qh, const __half* __restrict__ kh,
    const __half* __restrict__ vh, const int* __restrict__ seq_lens,
    __half* __restrict__ o) {
  extern __shared__ unsigned sm[];
  unsigned* Qs = sm;
  unsigned* Ks = Qs + 128 * QSW;
  unsigned* Vs = Ks + 64 * QSW;
  unsigned* Ps = Vs + 64 * QSW;
  const unsigned qs_b = (unsigned)__cvta_generic_to_shared(Qs);
  const unsigned ks_b = (unsigned)__cvta_generic_to_shared(Ks);
  const unsigned vs_b = (unsigned)__cvta_generic_to_shared(Vs);
  const unsigned ps_b = (unsigned)__cvta_generic_to_shared(Ps);

  const int tid = threadIdx.x, lane = tid & 31, warp = tid >> 5;
  const int q0 = blockIdx.x << 7, head = blockIdx.y;
  const int seqlen = seq_lens[0];
  const uint4* q4 = (const uint4*)qh;
  const uint4* k4 = (const uint4*)kh;
  const uint4* v4 = (const uint4*)vh;
  const int rs8 = D_MODEL / 8;
  const int h8 = head * 16;
  const int la = lane & 7, lb = (lane >> 3) & 1, lc2 = lane >> 4;
  const int rq = lane >> 2, tq = lane & 3;
  const int r_own = warp * 16 + rq;

  const unsigned a_off = qs_b + ((warp * 16 + la + 8 * lb) * QSW + 4 * lc2) * 4;
  const unsigned b_off = ks_b + ((la + 8 * lc2) * QSW + 4 * lb) * 4;
  const unsigned v_off = vs_b + ((la + 8 * lb) * QSW + 4 * lc2) * 4;
  const unsigned p_off = ps_b + ((warp * 16 + la + 8 * lb) * PSW + 4 * lc2) * 4;

  // loader mapping for tiles: idx = tid + 256*i -> r = idx>>4, c8 = idx&15
  const int ldr = tid >> 4, ldc8 = tid & 15;

  // Q tile via cp.async as well (128 rows x 16 uint4)
#pragma unroll
  for (int i = 0; i < 8; i++) {
    int r = ldr + (i << 4);
    CP_ASYNC16(qs_b + (r * QSW + 4 * ldc8) * 4,
               (const void*)&q4[(size_t)(q0 + r) * rs8 + h8 + ldc8]);
  }
  CP_COMMIT();

  float m0r = -INFINITY, m1r = -INFINITY, l0 = 0.f, l1 = 0.f;
  float oac[16][4];
#pragma unroll
  for (int j = 0; j < 16; j++)
#pragma unroll
    for (int u = 0; u < 4; u++) oac[j][u] = 0.f;

  for (int kt = 0; kt < 64; kt++) {
    __syncthreads();  // prev PV done (Ks/Vs free); also guards Qs on iter 0
    // fill K/V tiles for this step via cp.async (64 rows x 16 uint4 each)
#pragma unroll
    for (int i = 0; i < 4; i++) {
      int r = ldr + (i << 4);
      size_t grow = (size_t)((kt << 6) + r) * rs8 + h8 + ldc8;
      CP_ASYNC16(ks_b + (r * QSW + 4 * ldc8) * 4, (const void*)&k4[grow]);
      CP_ASYNC16(vs_b + (r * QSW + 4 * ldc8) * 4, (const void*)&v4[grow]);
    }
    CP_COMMIT();
    CP_WAIT0();
    __syncthreads();

    // S = Q K^T : m16 (warp rows) x n64, k=128 in 8 k16-steps
    float sacc[8][4];
#pragma unroll
    for (int j = 0; j < 8; j++)
#pragma unroll
      for (int u = 0; u < 4; u++) sacc[j][u] = 0.f;

#pragma unroll
    for (int s = 0; s < 8; s++) {
      unsigned a[4];
      LDSM4(a[0], a[1], a[2], a[3], a_off + 32 * s);
#pragma unroll
      for (int jp = 0; jp < 4; jp++) {
        unsigned bb[4];
        LDSM4(bb[0], bb[1], bb[2], bb[3],
              b_off + jp * (16 * QSW * 4) + 32 * s);
        mma16(sacc[2 * jp], a, &bb[0]);
        mma16(sacc[2 * jp + 1], a, &bb[2]);
      }
    }

    // mask (ragged tail only)
    if (((kt << 6) + 63) >= seqlen) {
#pragma unroll
      for (int j = 0; j < 8; j++) {
        int c = (kt << 6) + (j << 3) + 2 * tq;
        if (c >= seqlen) { sacc[j][0] = -1e30f; sacc[j][2] = -1e30f; }
        if (c + 1 >= seqlen) { sacc[j][1] = -1e30f; sacc[j][3] = -1e30f; }
      }
    }

    // register softmax
    float mx0 = -INFINITY, mx1 = -INFINITY;
#pragma unroll
    for (int j = 0; j < 8; j++) {
      mx0 = fmaxf(mx0, fmaxf(sacc[j][0], sacc[j][1]));
      mx1 = fmaxf(mx1, fmaxf(sacc[j][2], sacc[j][3]));
    }
    mx0 = fmaxf(mx0, __shfl_xor_sync(0xffffffffu, mx0, 1));
    mx0 = fmaxf(mx0, __shfl_xor_sync(0xffffffffu, mx0, 2));
    mx1 = fmaxf(mx1, __shfl_xor_sync(0xffffffffu, mx1, 1));
    mx1 = fmaxf(mx1, __shfl_xor_sync(0xffffffffu, mx1, 2));
    float mn0 = fmaxf(m0r, mx0), mn1 = fmaxf(m1r, mx1);
    float co0 = __expf(m0r - mn0), co1 = __expf(m1r - mn1);
    float s0 = 0.f, s1 = 0.f;
#pragma unroll
    for (int j = 0; j < 8; j++) {
      float p0 = __expf(sacc[j][0] - mn0);
      float p1 = __expf(sacc[j][1] - mn0);
      float p2 = __expf(sacc[j][2] - mn1);
      float p3 = __expf(sacc[j][3] - mn1);
      s0 += p0 + p1;
      s1 += p2 + p3;
      __half2 hp0 = __floats2half2_rn(p0, p1);
      __half2 hp1 = __floats2half2_rn(p2, p3);
      Ps[r_own * PSW + 4 * j + tq] = *(unsigned*)&hp0;
      Ps[(r_own + 8) * PSW + 4 * j + tq] = *(unsigned*)&hp1;
    }
    s0 += __shfl_xor_sync(0xffffffffu, s0, 1);
    s0 += __shfl_xor_sync(0xffffffffu, s0, 2);
    s1 += __shfl_xor_sync(0xffffffffu, s1, 1);
    s1 += __shfl_xor_sync(0xffffffffu, s1, 2);
    l0 = l0 * co0 + s0;
    l1 = l1 * co1 + s1;
    m0r = mn0;
    m1r = mn1;
#pragma unroll
    for (int j = 0; j < 16; j++) {
      oac[j][0] *= co0;
      oac[j][1] *= co0;
      oac[j][2] *= co1;
      oac[j][3] *= co1;
    }
    __syncwarp();  // Ps rows are per-warp private

    // O += P V : m16 x n128, k=64 in 4 k16-steps; V via ldmatrix.trans
#pragma unroll
    for (int s = 0; s < 4; s++) {
      unsigned pa[4];
      LDSM4(pa[0], pa[1], pa[2], pa[3], p_off + 32 * s);
#pragma unroll
      for (int jp = 0; jp < 8; jp++) {
        unsigned vb[4];
        LDSM4T(vb[0], vb[1], vb[2], vb[3],
               v_off + s * (16 * QSW * 4) + 32 * jp);
        mma16(oac[2 * jp], pa, &vb[0]);
        mma16(oac[2 * jp + 1], pa, &vb[2]);
      }
    }
  }

  float i0 = 1.f / l0, i1 = 1.f / l1;
  __half2* o2 = (__half2*)o;
#pragma unroll
  for (int j = 0; j < 16; j++) {
    int cw = head * 64 + 4 * j + tq;
    o2[(size_t)(q0 + r_own) * (D_MODEL / 2) + cw] =
        __floats2half2_rn(oac[j][0] * i0, oac[j][1] * i0);
    o2[(size_t)(q0 + r_own + 8) * (D_MODEL / 2) + cw] =
        __floats2half2_rn(oac[j][2] * i1, oac[j][3] * i1);
  }
}

// ---------------- launch ----------------
extern "C" void kernel_launch(void* const* d_in, const int* in_sizes, int n_in,
                              void* d_out, int out_size) {
  const float* x = (const float*)d_in[0];
  const int* seq_lens = (const int*)d_in[1];
  const int* grid_sizes = (const int*)d_in[2];
  const float* fcos = (const float*)d_in[3];
  const float* fsin = (const float*)d_in[4];
  const float* Wq = (const float*)d_in[5];
  const float* bq = (const float*)d_in[6];
  const float* Wk = (const float*)d_in[7];
  const float* bk = (const float*)d_in[8];
  const float* Wv = (const float*)d_in[9];
  const float* bv = (const float*)d_in[10];
  const float* Wo = (const float*)d_in[11];
  const float* bo = (const float*)d_in[12];
  const float* gq = (const float*)d_in[13];
  const float* gk = (const float*)d_in[14];
  float* out = (float*)d_out;

  void *pq, *pk, *pqh, *pkh, *pvh, *pao, *pxh, *pwh;
  cudaGetSymbolAddress(&pq, g_q);
  cudaGetSymbolAddress(&pk, g_k);
  cudaGetSymbolAddress(&pqh, g_qh);
  cudaGetSymbolAddress(&pkh, g_kh);
  cudaGetSymbolAddress(&pvh, g_vh);
  cudaGetSymbolAddress(&pao, g_ao);
  cudaGetSymbolAddress(&pxh, g_xh);
  cudaGetSymbolAddress(&pwh, g_wh);
  float* fq = (float*)pq;
  float* fk = (float*)pk;
  __half* fqh = (__half*)pqh;
  __half* fkh = (__half*)pkh;
  __half* fvh = (__half*)pvh;
  __half* fao = (__half*)pao;
  __half* fxh = (__half*)pxh;
  __half* fwh = (__half*)pwh;

  // convert weights + x to fp16
  {
    int n4max = (L_SEQ * D_MODEL) / 4;
    dim3 gr((n4max + 255) / 256, 1, 5);
    to_half<<<gr, 256>>>(Wq, Wk, Wv, Wo, x);
  }

  // fused QKV projection: z0->q f32, z1->k f32, z2->v fp16
  dim3 gqkv(D_MODEL / 128, L_SEQ / 128, 3);
  gemm_f16<<<gqkv, 256>>>(fxh, fwh, fwh + W_ELEMS, fwh + 2 * W_ELEMS,
                          bq, bk, bv, fq, fk, fvh);

  rmsnorm_rope<<<dim3(L_SEQ, 2), 256>>>(fq, fk, fqh, fkh, gq, gk, grid_sizes,
                                        fcos, fsin);

  cudaFuncSetAttribute(attn_f16, cudaFuncAttributeMaxDynamicSharedMemorySize,
                       ATTN_SMEM);
  attn_f16<<<dim3(L_SEQ / 128, N_HEADS), 256, ATTN_SMEM>>>(fqh, fkh, fvh,
                                                           seq_lens, fao);

  // output projection (zi=0 -> f32 out)
  dim3 go(D_MODEL / 128, L_SEQ / 128, 1);
  gemm_f16<<<go, 256>>>(fao, fwh + 3 * W_ELEMS, fwh + 3 * W_ELEMS,
                        fwh + 3 * W_ELEMS, bo, bo, bo, out, out, fvh);
}

// round 13
// speedup vs baseline: 2.5589x; 1.1286x over previous
#include <cuda_runtime.h>
#include <cuda_fp16.h>
#include <cstdint>
#include <stdint.h>
#include <math.h>

#define L_SEQ 4096
#define D_MODEL 1536
#define N_HEADS 12
#define D_HEAD 128
#define C_HALF 64   // d/2
#define ROPE_C1 22
#define ROPE_C2 21
#define W_ELEMS (D_MODEL * D_MODEL)

// ---------------- scratch (no allocations allowed) ----------------
__device__ float g_q[L_SEQ * D_MODEL];   // f32 q from GEMM (pre-norm)
__device__ float g_k[L_SEQ * D_MODEL];   // f32 k from GEMM (pre-norm)
__device__ __half g_qh[L_SEQ * D_MODEL]; // fp16 q (normed+rope+scaled)
__device__ __half g_kh[L_SEQ * D_MODEL]; // fp16 k
__device__ __half g_vh[L_SEQ * D_MODEL]; // fp16 v
__device__ __half g_ao[L_SEQ * D_MODEL]; // fp16 attention output
__device__ __half g_xh[L_SEQ * D_MODEL]; // fp16 x
__device__ __half g_wh[4 * W_ELEMS];     // fp16 Wq,Wk,Wv,Wo

// ---------------- mma helpers ----------------
__device__ __forceinline__ void mma16(float* c, const unsigned* a,
                                      const unsigned* b) {
  asm volatile(
      "mma.sync.aligned.m16n8k16.row.col.f32.f16.f16.f32 "
      "{%0,%1,%2,%3},{%4,%5,%6,%7},{%8,%9},{%0,%1,%2,%3};\n"
      : "+f"(c[0]), "+f"(c[1]), "+f"(c[2]), "+f"(c[3])
      : "r"(a[0]), "r"(a[1]), "r"(a[2]), "r"(a[3]), "r"(b[0]), "r"(b[1]));
}

#define LDSM4(r0, r1, r2, r3, addr)                                      \
  asm volatile("ldmatrix.sync.aligned.m8n8.x4.shared.b16 {%0,%1,%2,%3},[%4];" \
               : "=r"(r0), "=r"(r1), "=r"(r2), "=r"(r3) : "r"(addr))
#define LDSM4T(r0, r1, r2, r3, addr)                                     \
  asm volatile(                                                          \
      "ldmatrix.sync.aligned.m8n8.x4.trans.shared.b16 {%0,%1,%2,%3},[%4];" \
      : "=r"(r0), "=r"(r1), "=r"(r2), "=r"(r3) : "r"(addr))

// cp.async helpers (16B, cache-global)
#define CP_ASYNC16(dst, src)                                        \
  asm volatile("cp.async.cg.shared.global [%0], [%1], 16;" ::       \
                   "r"(dst), "l"(src))
#define CP_COMMIT() asm volatile("cp.async.commit_group;" ::: "memory")
#define CP_WAIT0() asm volatile("cp.async.wait_group 0;" ::: "memory")
#define CP_WAIT1() asm volatile("cp.async.wait_group 1;" ::: "memory")

// ---------------- fp16 conversion of weights + x ----------------
__global__ __launch_bounds__(256) void to_half(
    const float* __restrict__ wq, const float* __restrict__ wk,
    const float* __restrict__ wv, const float* __restrict__ wo,
    const float* __restrict__ x) {
  const int zi = blockIdx.z;
  const float4* src;
  __half2* dst;
  int n4;
  if (zi < 4) {
    src = (const float4*)((zi == 0) ? wq : (zi == 1) ? wk : (zi == 2) ? wv
                                                                      : wo);
    dst = ((__half2*)g_wh) + (size_t)zi * (W_ELEMS / 2);
    n4 = W_ELEMS / 4;
  } else {
    src = (const float4*)x;
    dst = (__half2*)g_xh;
    n4 = (L_SEQ * D_MODEL) / 4;
  }
  int idx = blockIdx.x * 256 + threadIdx.x;
  if (idx < n4) {
    float4 t = src[idx];
    dst[2 * idx] = __floats2half2_rn(t.x, t.y);
    dst[2 * idx + 1] = __floats2half2_rn(t.z, t.w);
  }
}

// ---------------- fp16 GEMM: C[M,N] = A * W^T + bias ----------------
// 128x128 tile, BK=64, 256 threads (8 warps, 2m x 4n), warp 64x32.
// zi selects weights/bias/output; zi==2 writes fp16 (v), else fp32.
#define GSW 36  // row stride in words (64 halves + 8 pad = 144B)
__global__ __launch_bounds__(256, 2) void gemm_f16(
    const __half* __restrict__ Ah,
    const __half* __restrict__ Wm0, const __half* __restrict__ Wm1,
    const __half* __restrict__ Wm2,
    const float* __restrict__ bz0, const float* __restrict__ bz1,
    const float* __restrict__ bz2,
    float* __restrict__ Cf0, float* __restrict__ Cf1,
    __half* __restrict__ Ch2) {
  const int zi = blockIdx.z;
  const __half* Wmat = (zi == 0) ? Wm0 : (zi == 1) ? Wm1 : Wm2;
  const float* bias = (zi == 0) ? bz0 : (zi == 1) ? bz1 : bz2;

  __shared__ unsigned As[128 * GSW];
  __shared__ unsigned Bs[128 * GSW];
  const unsigned as_b = (unsigned)__cvta_generic_to_shared(As);
  const unsigned bs_b = (unsigned)__cvta_generic_to_shared(Bs);
  const int tid = threadIdx.x, lane = tid & 31, warp = tid >> 5;
  const int wm = warp >> 2, wn = warp & 3;
  const int m0 = blockIdx.y << 7, n0 = blockIdx.x << 7;
  const int K8 = D_MODEL / 8;  // 192 uint4 per row
  const uint4* A4 = (const uint4*)Ah;
  const uint4* W4 = (const uint4*)Wmat;
  const int la = lane & 7, lb = (lane >> 3) & 1, lc2 = lane >> 4;
  const int rq = lane >> 2, tq = lane & 3;

  // ldmatrix base addresses (bytes); per k16-step add 32*s
  unsigned a_base[4], b_base[2];
#pragma unroll
  for (int mf = 0; mf < 4; mf++)
    a_base[mf] =
        as_b + ((wm * 64 + mf * 16 + la + 8 * lb) * GSW + 4 * lc2) * 4;
#pragma unroll
  for (int np = 0; np < 2; np++)
    b_base[np] = bs_b + ((wn * 32 + np * 16 + la + 8 * lc2) * GSW + 4 * lb) * 4;

  float acc[4][4][4];
#pragma unroll
  for (int mf = 0; mf < 4; mf++)
#pragma unroll
    for (int nf = 0; nf < 4; nf++)
#pragma unroll
      for (int u = 0; u < 4; u++) acc[mf][nf][u] = 0.f;

  // loader mapping: idx = tid + 256*i -> row = idx>>3 (0..127), c8 = idx&7
  const int ldrow = tid >> 3, ldc8 = tid & 7;
  uint4 ar[4], wr[4];
#pragma unroll
  for (int i = 0; i < 4; i++) {
    int r = ldrow + 32 * i;
    ar[i] = A4[(size_t)(m0 + r) * K8 + ldc8];
    wr[i] = W4[(size_t)(n0 + r) * K8 + ldc8];
  }

  for (int k0 = 0; k0 < D_MODEL; k0 += 64) {
    __syncthreads();
#pragma unroll
    for (int i = 0; i < 4; i++) {
      int r = ldrow + 32 * i;
      int base = r * GSW + 4 * ldc8;
      *(uint4*)&As[base] = ar[i];
      *(uint4*)&Bs[base] = wr[i];
    }
    __syncthreads();
    const int kn = (k0 + 64 < D_MODEL) ? (k0 + 64) : k0;
#pragma unroll
    for (int i = 0; i < 4; i++) {
      int r = ldrow + 32 * i;
      ar[i] = A4[(size_t)(m0 + r) * K8 + (kn >> 3) + ldc8];
      wr[i] = W4[(size_t)(n0 + r) * K8 + (kn >> 3) + ldc8];
    }
#pragma unroll
    for (int s = 0; s < 4; s++) {
      unsigned a[4][4], bq[2][4];
#pragma unroll
      for (int mf = 0; mf < 4; mf++)
        LDSM4(a[mf][0], a[mf][1], a[mf][2], a[mf][3], a_base[mf] + 32 * s);
#pragma unroll
      for (int np = 0; np < 2; np++)
        LDSM4(bq[np][0], bq[np][1], bq[np][2], bq[np][3], b_base[np] + 32 * s);
#pragma unroll
      for (int mf = 0; mf < 4; mf++)
#pragma unroll
        for (int np = 0; np < 2; np++) {
          mma16(acc[mf][2 * np], a[mf], &bq[np][0]);
          mma16(acc[mf][2 * np + 1], a[mf], &bq[np][2]);
        }
    }
  }

#pragma unroll
  for (int mf = 0; mf < 4; mf++) {
    int r = m0 + wm * 64 + mf * 16 + rq;
#pragma unroll
    for (int nf = 0; nf < 4; nf++) {
      int c = n0 + wn * 32 + 8 * nf + 2 * tq;
      float bb0 = bias[c], bb1 = bias[c + 1];
      float v00 = acc[mf][nf][0] + bb0, v01 = acc[mf][nf][1] + bb1;
      float v10 = acc[mf][nf][2] + bb0, v11 = acc[mf][nf][3] + bb1;
      if (zi == 2) {
        *(__half2*)&Ch2[(size_t)r * D_MODEL + c] = __floats2half2_rn(v00, v01);
        *(__half2*)&Ch2[(size_t)(r + 8) * D_MODEL + c] =
            __floats2half2_rn(v10, v11);
      } else {
        float* Cf = (zi == 0) ? Cf0 : Cf1;
        float2 o0 = {v00, v01};
        *(float2*)&Cf[(size_t)r * D_MODEL + c] = o0;
        float2 o1 = {v10, v11};
        *(float2*)&Cf[(size_t)(r + 8) * D_MODEL + c] = o1;
      }
    }
  }
}

// ---------------- fused RMSNorm (* g) + RoPE -> fp16 ----------------
// grid (L, 2): y=0 -> q (with 1/sqrt(d) folded), y=1 -> k
__global__ __launch_bounds__(256) void rmsnorm_rope(
    const float* __restrict__ bufq, const float* __restrict__ bufk,
    __half* __restrict__ outq, __half* __restrict__ outk,
    const float* __restrict__ gqp, const float* __restrict__ gkp,
    const int* __restrict__ grid_sizes,
    const float* __restrict__ fcos, const float* __restrict__ fsin) {
  const int t = blockIdx.x;
  const int tid = threadIdx.x;
  const int isq = (blockIdx.y == 0);
  const float* row = (isq ? bufq : bufk) + (size_t)t * D_MODEL;
  __half2* orow = (__half2*)((isq ? outq : outk) + (size_t)t * D_MODEL);
  const float* g = isq ? gqp : gkp;
  const float post = isq ? 0.08838834764831845f : 1.0f;

  float ss = 0.f;
  for (int i = tid; i < D_MODEL; i += 256) {
    float xv = row[i];
    ss += xv * xv;
  }
#pragma unroll
  for (int o = 16; o; o >>= 1) ss += __shfl_xor_sync(0xffffffffu, ss, o);
  __shared__ float red[8];
  if ((tid & 31) == 0) red[tid >> 5] = ss;

  const int f = grid_sizes[0], h = grid_sizes[1], w = grid_sizes[2];
  const int sl = f * h * w;

  __shared__ float cs[C_HALF], sn[C_HALF];
  if (t < sl && tid < C_HALF) {
    int fi = t / (h * w);
    int rem = t - fi * h * w;
    int hi = rem / w;
    int wi = rem - hi * w;
    int jj = tid;
    int rowp = (jj < ROPE_C1) ? fi : ((jj < ROPE_C1 + ROPE_C2) ? hi : wi);
    cs[jj] = fcos[rowp * C_HALF + jj];
    sn[jj] = fsin[rowp * C_HALF + jj];
  }
  __syncthreads();
  float tot = red[0] + red[1] + red[2] + red[3] + red[4] + red[5] + red[6] + red[7];
  float rinv = rsqrtf(tot * (1.0f / D_MODEL) + 1e-6f);

  if (t < sl) {
    for (int p = tid; p < N_HEADS * C_HALF; p += 256) {
      int head = p >> 6;
      int jj = p & 63;
      int i0 = head * D_HEAD + 2 * jj;
      float y0 = row[i0] * rinv * g[i0];
      float y1 = row[i0 + 1] * rinv * g[i0 + 1];
      float cv = cs[jj], sv = sn[jj];
      orow[i0 >> 1] = __floats2half2_rn((y0 * cv - y1 * sv) * post,
                                        (y0 * sv + y1 * cv) * post);
    }
  } else {
    for (int p = tid; p < D_MODEL / 2; p += 256) {
      int i0 = 2 * p;
      orow[p] = __floats2half2_rn(row[i0] * rinv * g[i0] * post,
                                  row[i0 + 1] * rinv * g[i0 + 1] * post);
    }
  }
}

// ---------------- fp16 flash attention (ldmatrix + m16n8k16) -------------
// grid (L/128, N_HEADS), 256 threads (8 warps). Q tile 128, KV tile 64.
// K/V double-buffered via cp.async (pipeline depth 1); P fed to PV MMA
// directly from registers (FA-2 fragment identity) -> no Ps smem.
#define QSW 68
#define KVW (64 * QSW)                    // words per K or V tile
#define ATTN_WORDS (128 * QSW + 4 * KVW)  // Q + 2x(K,V)
#define ATTN_SMEM (ATTN_WORDS * 4)

__global__ __launch_bounds__(256, 2) void attn_f16(
    const __half* __restrict__ qh, const __half* __restrict__ kh,
    const __half* __restrict__ vh, const int* __restrict__ seq_lens,
    __half* __restrict__ o) {
  extern __shared__ unsigned sm[];
  unsigned* Qs = sm;
  unsigned* Ks0 = Qs + 128 * QSW;  // buffers: Ks0, Vs0, Ks1, Vs1
  const unsigned qs_b = (unsigned)__cvta_generic_to_shared(Qs);
  const unsigned ks_b = (unsigned)__cvta_generic_to_shared(Ks0);
  const unsigned vs_b = ks_b + KVW * 4;
  const unsigned kvstr = 2 * KVW * 4;  // bytes between buffer pairs

  const int tid = threadIdx.x, lane = tid & 31, warp = tid >> 5;
  const int q0 = blockIdx.x << 7, head = blockIdx.y;
  const int seqlen = seq_lens[0];
  const uint4* q4 = (const uint4*)qh;
  const uint4* k4 = (const uint4*)kh;
  const uint4* v4 = (const uint4*)vh;
  const int rs8 = D_MODEL / 8;
  const int h8 = head * 16;
  const int la = lane & 7, lb = (lane >> 3) & 1, lc2 = lane >> 4;
  const int rq = lane >> 2, tq = lane & 3;
  const int r_own = warp * 16 + rq;

  const unsigned a_off = qs_b + ((warp * 16 + la + 8 * lb) * QSW + 4 * lc2) * 4;
  const unsigned b_off0 = ks_b + ((la + 8 * lc2) * QSW + 4 * lb) * 4;
  const unsigned v_off0 = vs_b + ((la + 8 * lb) * QSW + 4 * lc2) * 4;

  // loader mapping: idx = tid + 256*i -> r = idx>>4, c8 = idx&15
  const int ldr = tid >> 4, ldc8 = tid & 15;

  // Q tile via cp.async (group 1)
#pragma unroll
  for (int i = 0; i < 8; i++) {
    int r = ldr + (i << 4);
    CP_ASYNC16(qs_b + (r * QSW + 4 * ldc8) * 4,
               (const void*)&q4[(size_t)(q0 + r) * rs8 + h8 + ldc8]);
  }
  CP_COMMIT();
  // K/V tile 0 into buffer 0 (group 2)
#pragma unroll
  for (int i = 0; i < 4; i++) {
    int r = ldr + (i << 4);
    size_t grow = (size_t)r * rs8 + h8 + ldc8;
    CP_ASYNC16(ks_b + (r * QSW + 4 * ldc8) * 4, (const void*)&k4[grow]);
    CP_ASYNC16(vs_b + (r * QSW + 4 * ldc8) * 4, (const void*)&v4[grow]);
  }
  CP_COMMIT();

  float m0r = -INFINITY, m1r = -INFINITY, l0 = 0.f, l1 = 0.f;
  float oac[16][4];
#pragma unroll
  for (int j = 0; j < 16; j++)
#pragma unroll
    for (int u = 0; u < 4; u++) oac[j][u] = 0.f;

  for (int kt = 0; kt < 64; kt++) {
    const int b = kt & 1;
    __syncthreads();  // all threads done reading buffer b^1 (iteration kt-1)
    if (kt < 63) {    // prefetch tile kt+1 into buffer b^1
#pragma unroll
      for (int i = 0; i < 4; i++) {
        int r = ldr + (i << 4);
        size_t grow = (size_t)(((kt + 1) << 6) + r) * rs8 + h8 + ldc8;
        unsigned boff = (b ^ 1) * kvstr + (r * QSW + 4 * ldc8) * 4;
        CP_ASYNC16(ks_b + boff, (const void*)&k4[grow]);
        CP_ASYNC16(vs_b + boff, (const void*)&v4[grow]);
      }
      CP_COMMIT();
      CP_WAIT1();  // tile kt (and Q) complete; kt+1 may be in flight
    } else {
      CP_WAIT0();
    }
    __syncthreads();  // tile kt visible to all threads

    const unsigned b_off = b_off0 + b * kvstr;
    const unsigned v_off = v_off0 + b * kvstr;

    // S = Q K^T : m16 (warp rows) x n64, k=128 in 8 k16-steps
    float sacc[8][4];
#pragma unroll
    for (int j = 0; j < 8; j++)
#pragma unroll
      for (int u = 0; u < 4; u++) sacc[j][u] = 0.f;

#pragma unroll
    for (int s = 0; s < 8; s++) {
      unsigned a[4];
      LDSM4(a[0], a[1], a[2], a[3], a_off + 32 * s);
#pragma unroll
      for (int jp = 0; jp < 4; jp++) {
        unsigned bb[4];
        LDSM4(bb[0], bb[1], bb[2], bb[3],
              b_off + jp * (16 * QSW * 4) + 32 * s);
        mma16(sacc[2 * jp], a, &bb[0]);
        mma16(sacc[2 * jp + 1], a, &bb[2]);
      }
    }

    // mask (ragged tail only)
    if (((kt << 6) + 63) >= seqlen) {
#pragma unroll
      for (int j = 0; j < 8; j++) {
        int c = (kt << 6) + (j << 3) + 2 * tq;
        if (c >= seqlen) { sacc[j][0] = -1e30f; sacc[j][2] = -1e30f; }
        if (c + 1 >= seqlen) { sacc[j][1] = -1e30f; sacc[j][3] = -1e30f; }
      }
    }

    // register softmax; P packed directly into PV A-fragments
    float mx0 = -INFINITY, mx1 = -INFINITY;
#pragma unroll
    for (int j = 0; j < 8; j++) {
      mx0 = fmaxf(mx0, fmaxf(sacc[j][0], sacc[j][1]));
      mx1 = fmaxf(mx1, fmaxf(sacc[j][2], sacc[j][3]));
    }
    mx0 = fmaxf(mx0, __shfl_xor_sync(0xffffffffu, mx0, 1));
    mx0 = fmaxf(mx0, __shfl_xor_sync(0xffffffffu, mx0, 2));
    mx1 = fmaxf(mx1, __shfl_xor_sync(0xffffffffu, mx1, 1));
    mx1 = fmaxf(mx1, __shfl_xor_sync(0xffffffffu, mx1, 2));
    float mn0 = fmaxf(m0r, mx0), mn1 = fmaxf(m1r, mx1);
    float co0 = __expf(m0r - mn0), co1 = __expf(m1r - mn1);
    float s0 = 0.f, s1 = 0.f;
    unsigned pfrag[4][4];
#pragma unroll
    for (int j = 0; j < 8; j++) {
      float p0 = __expf(sacc[j][0] - mn0);
      float p1 = __expf(sacc[j][1] - mn0);
      float p2 = __expf(sacc[j][2] - mn1);
      float p3 = __expf(sacc[j][3] - mn1);
      s0 += p0 + p1;
      s1 += p2 + p3;
      __half2 hp0 = __floats2half2_rn(p0, p1);  // row rq
      __half2 hp1 = __floats2half2_rn(p2, p3);  // row rq+8
      pfrag[j >> 1][(j & 1) * 2] = *(unsigned*)&hp0;
      pfrag[j >> 1][(j & 1) * 2 + 1] = *(unsigned*)&hp1;
    }
    s0 += __shfl_xor_sync(0xffffffffu, s0, 1);
    s0 += __shfl_xor_sync(0xffffffffu, s0, 2);
    s1 += __shfl_xor_sync(0xffffffffu, s1, 1);
    s1 += __shfl_xor_sync(0xffffffffu, s1, 2);
    l0 = l0 * co0 + s0;
    l1 = l1 * co1 + s1;
    m0r = mn0;
    m1r = mn1;
#pragma unroll
    for (int j = 0; j < 16; j++) {
      oac[j][0] *= co0;
      oac[j][1] *= co0;
      oac[j][2] *= co1;
      oac[j][3] *= co1;
    }

    // O += P V : m16 x n128, k=64 in 4 k16-steps; V via ldmatrix.trans,
    // P from registers
#pragma unroll
    for (int s = 0; s < 4; s++) {
#pragma unroll
      for (int jp = 0; jp < 8; jp++) {
        unsigned vb[4];
        LDSM4T(vb[0], vb[1], vb[2], vb[3],
               v_off + s * (16 * QSW * 4) + 32 * jp);
        mma16(oac[2 * jp], pfrag[s], &vb[0]);
        mma16(oac[2 * jp + 1], pfrag[s], &vb[2]);
      }
    }
  }

  float i0 = 1.f / l0, i1 = 1.f / l1;
  __half2* o2 = (__half2*)o;
#pragma unroll
  for (int j = 0; j < 16; j++) {
    int cw = head * 64 + 4 * j + tq;
    o2[(size_t)(q0 + r_own) * (D_MODEL / 2) + cw] =
        __floats2half2_rn(oac[j][0] * i0, oac[j][1] * i0);
    o2[(size_t)(q0 + r_own + 8) * (D_MODEL / 2) + cw] =
        __floats2half2_rn(oac[j][2] * i1, oac[j][3] * i1);
  }
}

// ---------------- launch ----------------
extern "C" void kernel_launch(void* const* d_in, const int* in_sizes, int n_in,
                              void* d_out, int out_size) {
  const float* x = (const float*)d_in[0];
  const int* seq_lens = (const int*)d_in[1];
  const int* grid_sizes = (const int*)d_in[2];
  const float* fcos = (const float*)d_in[3];
  const float* fsin = (const float*)d_in[4];
  const float* Wq = (const float*)d_in[5];
  const float* bq = (const float*)d_in[6];
  const float* Wk = (const float*)d_in[7];
  const float* bk = (const float*)d_in[8];
  const float* Wv = (const float*)d_in[9];
  const float* bv = (const float*)d_in[10];
  const float* Wo = (const float*)d_in[11];
  const float* bo = (const float*)d_in[12];
  const float* gq = (const float*)d_in[13];
  const float* gk = (const float*)d_in[14];
  float* out = (float*)d_out;

  void *pq, *pk, *pqh, *pkh, *pvh, *pao, *pxh, *pwh;
  cudaGetSymbolAddress(&pq, g_q);
  cudaGetSymbolAddress(&pk, g_k);
  cudaGetSymbolAddress(&pqh, g_qh);
  cudaGetSymbolAddress(&pkh, g_kh);
  cudaGetSymbolAddress(&pvh, g_vh);
  cudaGetSymbolAddress(&pao, g_ao);
  cudaGetSymbolAddress(&pxh, g_xh);
  cudaGetSymbolAddress(&pwh, g_wh);
  float* fq = (float*)pq;
  float* fk = (float*)pk;
  __half* fqh = (__half*)pqh;
  __half* fkh = (__half*)pkh;
  __half* fvh = (__half*)pvh;
  __half* fao = (__half*)pao;
  __half* fxh = (__half*)pxh;
  __half* fwh = (__half*)pwh;

  // convert weights + x to fp16
  {
    int n4max = (L_SEQ * D_MODEL) / 4;
    dim3 gr((n4max + 255) / 256, 1, 5);
    to_half<<<gr, 256>>>(Wq, Wk, Wv, Wo, x);
  }

  // fused QKV projection: z0->q f32, z1->k f32, z2->v fp16
  dim3 gqkv(D_MODEL / 128, L_SEQ / 128, 3);
  gemm_f16<<<gqkv, 256>>>(fxh, fwh, fwh + W_ELEMS, fwh + 2 * W_ELEMS,
                          bq, bk, bv, fq, fk, fvh);

  rmsnorm_rope<<<dim3(L_SEQ, 2), 256>>>(fq, fk, fqh, fkh, gq, gk, grid_sizes,
                                        fcos, fsin);

  cudaFuncSetAttribute(attn_f16, cudaFuncAttributeMaxDynamicSharedMemorySize,
                       ATTN_SMEM);
  attn_f16<<<dim3(L_SEQ / 128, N_HEADS), 256, ATTN_SMEM>>>(fqh, fkh, fvh,
                                                           seq_lens, fao);

  // output projection (zi=0 -> f32 out)
  dim3 go(D_MODEL / 128, L_SEQ / 128, 1);
  gemm_f16<<<go, 256>>>(fao, fwh + 3 * W_ELEMS, fwh + 3 * W_ELEMS,
                        fwh + 3 * W_ELEMS, bo, bo, bo, out, out, fvh);
}